// round 13
// baseline (speedup 1.0000x reference)
#include <cuda_runtime.h>
#include <cuda_fp16.h>
#include <math.h>

// Problem constants
constexpr int S  = 1024;
constexpr int Mm = 128;
constexpr int D  = 1024;
constexpr int H  = 16;
constexpr int HD = 64;
constexpr int F  = 2048;
constexpr int L  = 8;
constexpr int TOT = S + 2 * Mm;     // 1280
constexpr int KHID = Mm + S;        // 1152

// ---------------- f32 scratch pool ----------------
constexpr size_t OFF_CAT  = 0;                          // 1280*1024
constexpr size_t OFF_TQKV = 9437184;                    // reused as fp16 area
constexpr size_t OFF_COS  = 18874368;
constexpr size_t OFF_SIN  = 18956288;
constexpr size_t POOL_SZ  = 19038208;
__device__ __align__(16) float g_pool[POOL_SZ];

// ---------------- fp16 scratch pool ----------------
constexpr size_t WL_STRIDE = 18874368;   // per-layer: 12*1048576 + 3*2097152
constexpr size_t BW_ALL   = 0;           // 8 layers of converted weights
constexpr size_t B_XH     = 150994944;   // 1280*1024
constexpr size_t B_AH     = 152305664;
constexpr size_t B_YH     = 153616384;
constexpr size_t B_GH     = 154927104;   // 1280*2048
constexpr size_t B_MEH    = 157548544;   // 8 * 128*1024
constexpr size_t HB_Q     = 158597120;   // 16*1024*64
constexpr size_t HB_QB    = 159645696;   // 16*128*64
constexpr size_t HB_QF    = 159776768;
constexpr size_t HB_K     = 159907840;   // 16*1280*64
constexpr size_t HB_V     = 161218560;
constexpr size_t HB_KF    = 162529280;   // 16*128*64
constexpr size_t HB_VF    = 162660352;
constexpr size_t BPOOL_SZ = 162791424;
__device__ __align__(16) __half g_poolhf[BPOOL_SZ];

__device__ __forceinline__ unsigned h2u(__half2 h) { return *(unsigned*)&h; }

// ---------------- rope tables ----------------
__global__ void k_tables(float* cosT, float* sinT) {
    int idx = blockIdx.x * blockDim.x + threadIdx.x;
    if (idx >= 1280 * 64) return;
    int p = idx >> 6;
    int d = idx & 63;
    int i = d & 31;
    double inv = pow(10000.0, -((double)i) / 32.0);
    double ang = (double)p * inv;
    cosT[idx] = (float)cos(ang);
    sinT[idx] = (float)sin(ang);
}

// ---------------- initial residual ----------------
__global__ void k_fillcat(float* cat, const int* __restrict__ ids,
                          const float* __restrict__ embed,
                          const float* __restrict__ beacon,
                          const float* __restrict__ forget) {
    int idx = blockIdx.x * blockDim.x + threadIdx.x;
    if (idx >= TOT * D) return;
    int row = idx >> 10;
    int d = idx & 1023;
    float v;
    if (row < S)            v = embed[(size_t)ids[row] * D + d];
    else if (row < S + Mm)  v = beacon[(size_t)(row - S) * D + d];
    else                    v = forget[(size_t)(row - S - Mm) * D + d];
    cat[idx] = v;
}

// ---------------- rmsnorm -> fp16, fused gated-output ----------------
__global__ void k_rms(const float* __restrict__ in, const float* __restrict__ w,
                      __half* __restrict__ oh,
                      const float* __restrict__ mem, float* __restrict__ outg) {
    int row = blockIdx.x;
    int t = threadIdx.x;
    if (row >= TOT) {
        int idx = (row - TOT) * 1024 + t * 4;
        float4 bcn = *(const float4*)(in + (size_t)S * D + idx);
        float4 fgt = *(const float4*)(in + (size_t)(S + Mm) * D + idx);
        float4 mv  = *(const float4*)(mem + idx);
        float4 o;
        float g;
        g = 1.0f / (1.0f + expf(-fgt.x)); o.x = mv.x * g + bcn.x * (1.0f - g);
        g = 1.0f / (1.0f + expf(-fgt.y)); o.y = mv.y * g + bcn.y * (1.0f - g);
        g = 1.0f / (1.0f + expf(-fgt.z)); o.z = mv.z * g + bcn.z * (1.0f - g);
        g = 1.0f / (1.0f + expf(-fgt.w)); o.w = mv.w * g + bcn.w * (1.0f - g);
        *(float4*)(outg + idx) = o;
        return;
    }
    const float* r = in + (size_t)row * D;
    float4 v = *(const float4*)(r + t * 4);
    float ss = fmaf(v.x, v.x, fmaf(v.y, v.y, fmaf(v.z, v.z, v.w * v.w)));
    #pragma unroll
    for (int o = 16; o; o >>= 1) ss += __shfl_xor_sync(0xffffffffu, ss, o);
    __shared__ float wsum[8];
    __shared__ float sc;
    if ((t & 31) == 0) wsum[t >> 5] = ss;
    __syncthreads();
    if (t == 0) {
        float tot = 0.0f;
        #pragma unroll
        for (int i = 0; i < 8; i++) tot += wsum[i];
        sc = rsqrtf(tot / (float)D + 1e-5f);
    }
    __syncthreads();
    float scale = sc;
    float4 wv = *(const float4*)(w + t * 4);
    __half2 h01 = __floats2half2_rn(v.x * scale * wv.x, v.y * scale * wv.y);
    __half2 h23 = __floats2half2_rn(v.z * scale * wv.z, v.w * scale * wv.w);
    *(uint2*)(oh + (size_t)row * D + t * 4) = make_uint2(h2u(h01), h2u(h23));
}

// ---------------- weight transpose -> fp16, ALL layers ----------------
struct WcEnt { const float* src; __half* dh; int K; int N; int blkOff; size_t lsrc; };
struct WcArgs { WcEnt e[15]; };

__global__ void __launch_bounds__(256) k_wconv(WcArgs wa) {
    __shared__ float ts[32][33];
    int b = blockIdx.x;
    int lyr = blockIdx.y;
    int ei = 0;
    #pragma unroll
    for (int i = 14; i >= 1; i--) if (b >= wa.e[i].blkOff) { ei = i; break; }
    WcEnt E = wa.e[ei];
    const float* src = E.src + (size_t)lyr * E.lsrc;
    __half* dh = E.dh + (size_t)lyr * WL_STRIDE;
    int local = b - E.blkOff;
    int ntx = E.N >> 5;
    int tn = (local % ntx) << 5;
    int tk = (local / ntx) << 5;
    int t = threadIdx.x;
    {
        int row = t >> 3, c4 = (t & 7) << 2;
        float4 v = *(const float4*)(src + (size_t)(tk + row) * E.N + tn + c4);
        ts[row][c4 + 0] = v.x;
        ts[row][c4 + 1] = v.y;
        ts[row][c4 + 2] = v.z;
        ts[row][c4 + 3] = v.w;
    }
    __syncthreads();
    {
        int n = t >> 3, kq = (t & 7) << 2;
        __half2 h01 = __floats2half2_rn(ts[kq + 0][n], ts[kq + 1][n]);
        __half2 h23 = __floats2half2_rn(ts[kq + 2][n], ts[kq + 3][n]);
        *(uint2*)(dh + (size_t)(tn + n) * E.K + tk + kq) = make_uint2(h2u(h01), h2u(h23));
    }
}

// ---------------- plain f32 -> fp16 ----------------
__global__ void k_split(const float* __restrict__ src, __half* __restrict__ dh, int n) {
    int i = (blockIdx.x * 256 + threadIdx.x) * 8;
    if (i >= n) return;
    float4 a = *(const float4*)(src + i);
    float4 b = *(const float4*)(src + i + 4);
    uint4 o;
    o.x = h2u(__floats2half2_rn(a.x, a.y));
    o.y = h2u(__floats2half2_rn(a.z, a.w));
    o.z = h2u(__floats2half2_rn(b.x, b.y));
    o.w = h2u(__floats2half2_rn(b.z, b.w));
    *(uint4*)(dh + i) = o;
}

// ---------------- shared MMA helpers ----------------
__device__ __forceinline__ void mma16816(float* c, const unsigned* a, const unsigned* b) {
    asm volatile(
        "mma.sync.aligned.m16n8k16.row.col.f32.f16.f16.f32 "
        "{%0,%1,%2,%3}, {%4,%5,%6,%7}, {%8,%9}, {%0,%1,%2,%3};"
        : "+f"(c[0]), "+f"(c[1]), "+f"(c[2]), "+f"(c[3])
        : "r"(a[0]), "r"(a[1]), "r"(a[2]), "r"(a[3]), "r"(b[0]), "r"(b[1]));
}
__device__ __forceinline__ void ldsm4(unsigned* r, unsigned addr) {
    asm volatile("ldmatrix.sync.aligned.m8n8.x4.shared.b16 {%0,%1,%2,%3}, [%4];"
                 : "=r"(r[0]), "=r"(r[1]), "=r"(r[2]), "=r"(r[3]) : "r"(addr));
}
__device__ __forceinline__ void ldsm4t(unsigned* r, unsigned addr) {
    asm volatile("ldmatrix.sync.aligned.m8n8.x4.trans.shared.b16 {%0,%1,%2,%3}, [%4];"
                 : "=r"(r[0]), "=r"(r[1]), "=r"(r[2]), "=r"(r[3]) : "r"(addr));
}
__device__ __forceinline__ void cpasync16(unsigned saddr, const void* gptr) {
    asm volatile("cp.async.cg.shared.global [%0], [%1], 16;"
                 :: "r"(saddr), "l"(gptr) : "memory");
}
__device__ __forceinline__ void cp_commit() {
    asm volatile("cp.async.commit_group;" ::: "memory");
}
template<int NN> __device__ __forceinline__ void cp_wait() {
    asm volatile("cp.async.wait_group %0;" :: "n"(NN) : "memory");
}

// =======================================================================
// HMMA GEMM: C = A@B^T (+C). 128x128 tile, BK=64, 2-stage, 2 CTA/SM.
// outHalf: write fp16 to Ch instead of f32 C (accFlag must be 0).
// =======================================================================
struct GArgs {
    const __half* Ah[11];
    const __half* Bh[11];
    float* C[11];
    __half* Ch[11];
    int mRows[11];
};

constexpr int SMEM_HM = 65536;

__global__ void __launch_bounds__(256, 2) k_hmma(GArgs ga, int N, int K,
                                                 int accFlag, int outHalf) {
    extern __shared__ __align__(128) char smraw[];
    const int z = blockIdx.z;
    const int mbase = blockIdx.y << 7;
    if (mbase >= ga.mRows[z]) return;
    const int nbase = blockIdx.x << 7;

    const __half* Ah = ga.Ah[z];
    const __half* Bh = ga.Bh[z];

    const int t = threadIdx.x;
    const int l = t & 31;
    const int w = t >> 5;
    const int wr = w >> 2;
    const int wc = w & 3;
    const unsigned sb = (unsigned)__cvta_generic_to_shared(smraw);

    auto load_stage = [&](int c, int s) {
        unsigned stg = sb + (unsigned)s * 32768u;
        int k0 = c << 6;
        #pragma unroll
        for (int i = 0; i < 4; i++) {
            int id = t + i * 256;
            int row = id >> 3, kc = id & 7;
            unsigned soff = stg + (unsigned)row * 128u + (unsigned)((kc ^ (row & 7)) << 4);
            size_t ao = (size_t)(mbase + row) * K + k0 + kc * 8;
            size_t bo = (size_t)(nbase + row) * K + k0 + kc * 8;
            cpasync16(soff,          Ah + ao);
            cpasync16(soff + 16384u, Bh + bo);
        }
        cp_commit();
    };

    float acc[4][4][4];
    #pragma unroll
    for (int i = 0; i < 4; i++)
        #pragma unroll
        for (int j = 0; j < 4; j++)
            #pragma unroll
            for (int q = 0; q < 4; q++) acc[i][j][q] = 0.0f;

    const int nc = K >> 6;
    load_stage(0, 0);
    if (nc > 1) load_stage(1, 1);

    for (int c = 0; c < nc; c++) {
        if (c + 1 < nc) cp_wait<1>(); else cp_wait<0>();
        __syncthreads();
        unsigned stg = sb + (unsigned)(c & 1) * 32768u;
        #pragma unroll
        for (int ks = 0; ks < 4; ks++) {
            unsigned aH[4][4], bH[2][4];
            #pragma unroll
            for (int mt = 0; mt < 4; mt++) {
                int row = wr * 64 + mt * 16 + (l & 15);
                int chunk = ks * 2 + (l >> 4);
                unsigned off = stg + (unsigned)row * 128u + (unsigned)((chunk ^ (row & 7)) << 4);
                ldsm4(aH[mt], off);
            }
            #pragma unroll
            for (int p = 0; p < 2; p++) {
                int nrow = wc * 32 + p * 16 + ((l >> 1) & 8) + (l & 7);
                int chunk = ks * 2 + ((l >> 3) & 1);
                unsigned off = stg + 16384u + (unsigned)nrow * 128u +
                               (unsigned)((chunk ^ (nrow & 7)) << 4);
                ldsm4(bH[p], off);
            }
            #pragma unroll
            for (int mt = 0; mt < 4; mt++)
                #pragma unroll
                for (int j = 0; j < 4; j++)
                    mma16816(acc[mt][j], aH[mt], &bH[j >> 1][(j & 1) * 2]);
        }
        __syncthreads();
        if (c + 2 < nc) load_stage(c + 2, c & 1);
    }

    int r0 = wr * 64 + (l >> 2);
    int c0 = wc * 32 + (l & 3) * 2;
    if (outHalf) {
        __half* Ch = ga.Ch[z];
        #pragma unroll
        for (int mt = 0; mt < 4; mt++) {
            #pragma unroll
            for (int j = 0; j < 4; j++) {
                int row = mbase + r0 + mt * 16;
                int col = nbase + c0 + j * 8;
                *(unsigned*)(Ch + (size_t)row * N + col) =
                    h2u(__floats2half2_rn(acc[mt][j][0], acc[mt][j][1]));
                *(unsigned*)(Ch + (size_t)(row + 8) * N + col) =
                    h2u(__floats2half2_rn(acc[mt][j][2], acc[mt][j][3]));
            }
        }
    } else {
        float* C = ga.C[z];
        #pragma unroll
        for (int mt = 0; mt < 4; mt++) {
            #pragma unroll
            for (int j = 0; j < 4; j++) {
                int row = mbase + r0 + mt * 16;
                int col = nbase + c0 + j * 8;
                float2 v01 = { acc[mt][j][0], acc[mt][j][1] };
                float2 v23 = { acc[mt][j][2], acc[mt][j][3] };
                float* p0 = C + (size_t)row * N + col;
                float* p1 = C + (size_t)(row + 8) * N + col;
                if (accFlag) {
                    float2 o0 = *(const float2*)p0;
                    float2 o1 = *(const float2*)p1;
                    v01.x += o0.x; v01.y += o0.y;
                    v23.x += o1.x; v23.y += o1.y;
                }
                *(float2*)p0 = v01;
                *(float2*)p1 = v23;
            }
        }
    }
}

// =======================================================================
// Narrow HMMA GEMM: C = A@B^T (+C), f32 out. 128x64 tile, BK=64, 2-stage,
// 24KB/stage (48KB total), 2 CTA/SM. For wave-occupancy-bound GEMMs.
// =======================================================================
constexpr int SMEM_H64 = 49152;

__global__ void __launch_bounds__(256, 2) k_hmma64(const __half* __restrict__ Ah,
                                                   const __half* __restrict__ Bh,
                                                   float* __restrict__ C,
                                                   int N, int K, int accFlag) {
    extern __shared__ __align__(128) char smraw[];
    const int mbase = blockIdx.y << 7;
    const int nbase = blockIdx.x << 6;

    const int t = threadIdx.x;
    const int l = t & 31;
    const int w = t >> 5;
    const int wr = w >> 2;          // 0..1 -> 64 M rows
    const int wc = w & 3;           // 0..3 -> 16 N cols
    const unsigned sb = (unsigned)__cvta_generic_to_shared(smraw);

    auto load_stage = [&](int c, int s) {
        unsigned stg = sb + (unsigned)s * 24576u;
        int k0 = c << 6;
        #pragma unroll
        for (int i = 0; i < 4; i++) {
            int id = t + i * 256;
            int row = id >> 3, kc = id & 7;
            unsigned soff = stg + (unsigned)row * 128u + (unsigned)((kc ^ (row & 7)) << 4);
            cpasync16(soff, Ah + (size_t)(mbase + row) * K + k0 + kc * 8);
        }
        #pragma unroll
        for (int i = 0; i < 2; i++) {
            int id = t + i * 256;
            int row = id >> 3, kc = id & 7;
            unsigned soff = stg + 16384u + (unsigned)row * 128u +
                            (unsigned)((kc ^ (row & 7)) << 4);
            cpasync16(soff, Bh + (size_t)(nbase + row) * K + k0 + kc * 8);
        }
        cp_commit();
    };

    float acc[4][2][4];
    #pragma unroll
    for (int i = 0; i < 4; i++)
        #pragma unroll
        for (int j = 0; j < 2; j++)
            #pragma unroll
            for (int q = 0; q < 4; q++) acc[i][j][q] = 0.0f;

    const int nc = K >> 6;
    load_stage(0, 0);
    load_stage(1, 1);

    for (int c = 0; c < nc; c++) {
        if (c + 1 < nc) cp_wait<1>(); else cp_wait<0>();
        __syncthreads();
        unsigned stg = sb + (unsigned)(c & 1) * 24576u;
        #pragma unroll
        for (int ks = 0; ks < 4; ks++) {
            unsigned aH[4][4], bH[4];
            #pragma unroll
            for (int mt = 0; mt < 4; mt++) {
                int row = wr * 64 + mt * 16 + (l & 15);
                int chunk = ks * 2 + (l >> 4);
                unsigned off = stg + (unsigned)row * 128u + (unsigned)((chunk ^ (row & 7)) << 4);
                ldsm4(aH[mt], off);
            }
            {
                int nrow = wc * 16 + ((l >> 1) & 8) + (l & 7);
                int chunk = ks * 2 + ((l >> 3) & 1);
                unsigned off = stg + 16384u + (unsigned)nrow * 128u +
                               (unsigned)((chunk ^ (nrow & 7)) << 4);
                ldsm4(bH, off);
            }
            #pragma unroll
            for (int mt = 0; mt < 4; mt++)
                #pragma unroll
                for (int j = 0; j < 2; j++)
                    mma16816(acc[mt][j], aH[mt], &bH[j * 2]);
        }
        __syncthreads();
        if (c + 2 < nc) load_stage(c + 2, c & 1);
    }

    int r0 = wr * 64 + (l >> 2);
    int c0 = wc * 16 + (l & 3) * 2;
    #pragma unroll
    for (int mt = 0; mt < 4; mt++) {
        #pragma unroll
        for (int j = 0; j < 2; j++) {
            int row = mbase + r0 + mt * 16;
            int col = nbase + c0 + j * 8;
            float2 v01 = { acc[mt][j][0], acc[mt][j][1] };
            float2 v23 = { acc[mt][j][2], acc[mt][j][3] };
            float* p0 = C + (size_t)row * N + col;
            float* p1 = C + (size_t)(row + 8) * N + col;
            if (accFlag) {
                float2 o0 = *(const float2*)p0;
                float2 o1 = *(const float2*)p1;
                v01.x += o0.x; v01.y += o0.y;
                v23.x += o1.x; v23.y += o1.y;
            }
            *(float2*)p0 = v01;
            *(float2*)p1 = v23;
        }
    }
}

// =======================================================================
// Fused MLP: gh = silu(A@Bg^T) * (A@Bu^T), fp16 out. 128x64 tile.
// =======================================================================
__global__ void __launch_bounds__(256, 2) k_mlp(const __half* __restrict__ A,
                                                const __half* __restrict__ Bg,
                                                const __half* __restrict__ Bu,
                                                __half* __restrict__ Cg,
                                                int N, int K) {
    extern __shared__ __align__(128) char smraw[];
    const int mbase = blockIdx.y << 7;
    const int nbase = blockIdx.x << 6;

    const int t = threadIdx.x;
    const int l = t & 31;
    const int w = t >> 5;
    const int wr = w >> 2;
    const int wc = w & 3;
    const unsigned sb = (unsigned)__cvta_generic_to_shared(smraw);

    auto load_stage = [&](int c, int s) {
        unsigned stg = sb + (unsigned)s * 32768u;
        int k0 = c << 6;
        #pragma unroll
        for (int i = 0; i < 4; i++) {
            int id = t + i * 256;
            int row = id >> 3, kc = id & 7;
            unsigned soff = stg + (unsigned)row * 128u + (unsigned)((kc ^ (row & 7)) << 4);
            cpasync16(soff, A + (size_t)(mbase + row) * K + k0 + kc * 8);
        }
        #pragma unroll
        for (int i = 0; i < 2; i++) {
            int id = t + i * 256;
            int row = id >> 3, kc = id & 7;
            unsigned soff = stg + 16384u + (unsigned)row * 128u +
                            (unsigned)((kc ^ (row & 7)) << 4);
            size_t bo = (size_t)(nbase + row) * K + k0 + kc * 8;
            cpasync16(soff,         Bg + bo);
            cpasync16(soff + 8192u, Bu + bo);
        }
        cp_commit();
    };

    float ag[4][2][4], au[4][2][4];
    #pragma unroll
    for (int i = 0; i < 4; i++)
        #pragma unroll
        for (int j = 0; j < 2; j++)
            #pragma unroll
            for (int q = 0; q < 4; q++) { ag[i][j][q] = 0.0f; au[i][j][q] = 0.0f; }

    const int nc = K >> 6;
    load_stage(0, 0);
    load_stage(1, 1);

    for (int c = 0; c < nc; c++) {
        if (c + 1 < nc) cp_wait<1>(); else cp_wait<0>();
        __syncthreads();
        unsigned stg = sb + (unsigned)(c & 1) * 32768u;
        #pragma unroll
        for (int ks = 0; ks < 4; ks++) {
            unsigned aH[4][4], bG[4], bU[4];
            #pragma unroll
            for (int mt = 0; mt < 4; mt++) {
                int row = wr * 64 + mt * 16 + (l & 15);
                int chunk = ks * 2 + (l >> 4);
                unsigned off = stg + (unsigned)row * 128u + (unsigned)((chunk ^ (row & 7)) << 4);
                ldsm4(aH[mt], off);
            }
            {
                int nrow = wc * 16 + ((l >> 1) & 8) + (l & 7);
                int chunk = ks * 2 + ((l >> 3) & 1);
                unsigned off = stg + 16384u + (unsigned)nrow * 128u +
                               (unsigned)((chunk ^ (nrow & 7)) << 4);
                ldsm4(bG, off);
                ldsm4(bU, off + 8192u);
            }
            #pragma unroll
            for (int mt = 0; mt < 4; mt++)
                #pragma unroll
                for (int j = 0; j < 2; j++) {
                    mma16816(ag[mt][j], aH[mt], &bG[j * 2]);
                    mma16816(au[mt][j], aH[mt], &bU[j * 2]);
                }
        }
        __syncthreads();
        if (c + 2 < nc) load_stage(c + 2, c & 1);
    }

    int r0 = wr * 64 + (l >> 2);
    int c0 = wc * 16 + (l & 3) * 2;
    #pragma unroll
    for (int mt = 0; mt < 4; mt++) {
        #pragma unroll
        for (int j = 0; j < 2; j++) {
            int row = mbase + r0 + mt * 16;
            int col = nbase + c0 + j * 8;
            float g0 = ag[mt][j][0], g1 = ag[mt][j][1];
            float g2 = ag[mt][j][2], g3 = ag[mt][j][3];
            float v0 = g0 / (1.0f + expf(-g0)) * au[mt][j][0];
            float v1 = g1 / (1.0f + expf(-g1)) * au[mt][j][1];
            float v2 = g2 / (1.0f + expf(-g2)) * au[mt][j][2];
            float v3 = g3 / (1.0f + expf(-g3)) * au[mt][j][3];
            *(unsigned*)(Cg + (size_t)row * N + col)       = h2u(__floats2half2_rn(v0, v1));
            *(unsigned*)(Cg + (size_t)(row + 8) * N + col) = h2u(__floats2half2_rn(v2, v3));
        }
    }
}

// ---------------- rope + head-major reshape (fp16 in -> fp16 out) ----------------
struct RsOne {
    const __half* src;
    __half*       dst;
    int rows;
    int dstStride;
    int dstOff;
    int posBase;
    float scl;
};
struct RsArgs { RsOne e[11]; };

__global__ void k_reshape(RsArgs ra, const float* __restrict__ cosT,
                          const float* __restrict__ sinT) {
    RsOne a = ra.e[blockIdx.y];
    int idx = blockIdx.x * 256 + threadIdx.x;
    if (idx >= a.rows * 1024) return;
    int row = idx >> 10;
    int n = idx & 1023;
    int h = n >> 6;
    int d = n & 63;
    float v = __half2float(a.src[idx]);
    float o;
    if (a.posBase >= 0) {
        int pos = a.posBase + row;
        float partner = (d < 32)
            ? -__half2float(a.src[(size_t)row * 1024 + h * 64 + d + 32])
            :  __half2float(a.src[(size_t)row * 1024 + h * 64 + d - 32]);
        o = v * cosT[pos * 64 + d] + partner * sinT[pos * 64 + d];
    } else {
        o = v;
    }
    a.dst[((size_t)h * a.dstStride + a.dstOff + row) * 64 + d] = __float2half_rn(o * a.scl);
}

// ---------------- HMMA flash attention, z-batched, double-buffered K/V ----------------
struct AtArgs {
    const __half* Q[3];  int nq[3];
    const __half* K1[3]; const __half* V1[3]; int len1[3]; int hs1[3];
    const __half* K2[3]; const __half* V2[3]; int len2[3]; int hs2[3];
    int P[3]; __half* OutH[3];
};

__global__ void __launch_bounds__(128) k_attn(AtArgs aa) {
    const int z = blockIdx.z;
    const int qb = blockIdx.x * 64;
    if (qb >= aa.nq[z]) return;
    const int nq = aa.nq[z], len1 = aa.len1[z], hs1 = aa.hs1[z];
    const int len2 = aa.len2[z], hs2 = aa.hs2[z], P = aa.P[z];
    const __half* K1 = aa.K1[z]; const __half* V1 = aa.V1[z];
    const __half* K2 = aa.K2[z]; const __half* V2 = aa.V2[z];
    __half* OutH = aa.OutH[z];

    const int h = blockIdx.y;
    const int t = threadIdx.x;
    const int l = t & 31;
    const int w = t >> 5;

    __shared__ __align__(16) __half sm[16384];
    const unsigned sb = (unsigned)__cvta_generic_to_shared(sm);

    const __half* Qh = aa.Q[z] + (size_t)h * nq * 64;
    const int qrow = qb + w * 16 + (l >> 2);
    const int qcol = (l & 3) * 2;
    unsigned qfr[4][4];
    #pragma unroll
    for (int dt = 0; dt < 4; dt++) {
        qfr[dt][0] = *(const unsigned*)(Qh + (size_t)qrow * 64 + dt * 16 + qcol);
        qfr[dt][1] = *(const unsigned*)(Qh + (size_t)(qrow + 8) * 64 + dt * 16 + qcol);
        qfr[dt][2] = *(const unsigned*)(Qh + (size_t)qrow * 64 + dt * 16 + 8 + qcol);
        qfr[dt][3] = *(const unsigned*)(Qh + (size_t)(qrow + 8) * 64 + dt * 16 + 8 + qcol);
    }

    float oacc[8][4];
    #pragma unroll
    for (int i = 0; i < 8; i++)
        #pragma unroll
        for (int q = 0; q < 4; q++) oacc[i][q] = 0.0f;
    float m0 = -1e30f, m1 = -1e30f, ls0 = 0.0f, ls1 = 0.0f;

    const int total = len1 + len2;
    const int eff = min(total, P + qb + 64);
    const int ntk = (eff + 63) >> 6;
    const int wqmin = qb + w * 16;

    auto load_kv = [&](int kt, int s) {
        #pragma unroll
        for (int i = 0; i < 4; i++) {
            int id = t + i * 128;
            int row = id >> 3, kc = id & 7;
            int j = kt * 64 + row;
            const __half *kp, *vp;
            if (j < len1) {
                kp = K1 + (size_t)h * hs1 + (size_t)j * 64;
                vp = V1 + (size_t)h * hs1 + (size_t)j * 64;
            } else {
                kp = K2 + (size_t)h * hs2 + (size_t)(j - len1) * 64;
                vp = V2 + (size_t)h * hs2 + (size_t)(j - len1) * 64;
            }
            unsigned soff = sb + (unsigned)s * 16384u + (unsigned)row * 128u +
                            (unsigned)((kc ^ (row & 7)) << 4);
            cpasync16(soff,         kp + kc * 8);
            cpasync16(soff + 8192u, vp + kc * 8);
        }
        cp_commit();
    };

    load_kv(0, 0);

    for (int kt = 0; kt < ntk; kt++) {
        if (kt + 1 < ntk) { load_kv(kt + 1, (kt + 1) & 1); cp_wait<1>(); }
        else cp_wait<0>();
        __syncthreads();
        unsigned stg = sb + (unsigned)(kt & 1) * 16384u;

        float sacc[8][4];
        #pragma unroll
        for (int i = 0; i < 8; i++)
            #pragma unroll
            for (int q = 0; q < 4; q++) sacc[i][q] = 0.0f;
        #pragma unroll
        for (int p = 0; p < 4; p++) {
            int nrow = p * 16 + ((l >> 1) & 8) + (l & 7);
            #pragma unroll
            for (int dt = 0; dt < 4; dt++) {
                int chunk = dt * 2 + ((l >> 3) & 1);
                unsigned off = stg + (unsigned)nrow * 128u + (unsigned)((chunk ^ (nrow & 7)) << 4);
                unsigned kfr[4];
                ldsm4(kfr, off);
                mma16816(sacc[2 * p],     qfr[dt], kfr);
                mma16816(sacc[2 * p + 1], qfr[dt], kfr + 2);
            }
        }

        int kg0 = kt * 64;
        if (!(kg0 + 63 < P || kg0 + 63 - P <= wqmin)) {
            #pragma unroll
            for (int nt = 0; nt < 8; nt++) {
                int col = kg0 + nt * 8 + qcol;
                if (!(col < P || col - P <= qrow))         sacc[nt][0] = -1e30f;
                if (!(col + 1 < P || col + 1 - P <= qrow)) sacc[nt][1] = -1e30f;
                if (!(col < P || col - P <= qrow + 8))         sacc[nt][2] = -1e30f;
                if (!(col + 1 < P || col + 1 - P <= qrow + 8)) sacc[nt][3] = -1e30f;
            }
        }

        float tm0 = -1e30f, tm1 = -1e30f;
        #pragma unroll
        for (int nt = 0; nt < 8; nt++) {
            tm0 = fmaxf(tm0, fmaxf(sacc[nt][0], sacc[nt][1]));
            tm1 = fmaxf(tm1, fmaxf(sacc[nt][2], sacc[nt][3]));
        }
        tm0 = fmaxf(tm0, __shfl_xor_sync(0xffffffffu, tm0, 1));
        tm0 = fmaxf(tm0, __shfl_xor_sync(0xffffffffu, tm0, 2));
        tm1 = fmaxf(tm1, __shfl_xor_sync(0xffffffffu, tm1, 1));
        tm1 = fmaxf(tm1, __shfl_xor_sync(0xffffffffu, tm1, 2));
        float nm0 = fmaxf(m0, tm0), nm1 = fmaxf(m1, tm1);
        float cr0 = __expf(m0 - nm0), cr1 = __expf(m1 - nm1);
        ls0 *= cr0; ls1 *= cr1;
        #pragma unroll
        for (int nt = 0; nt < 8; nt++) {
            oacc[nt][0] *= cr0; oacc[nt][1] *= cr0;
            oacc[nt][2] *= cr1; oacc[nt][3] *= cr1;
        }
        m0 = nm0; m1 = nm1;
        #pragma unroll
        for (int nt = 0; nt < 8; nt++) {
            sacc[nt][0] = __expf(sacc[nt][0] - nm0);
            sacc[nt][1] = __expf(sacc[nt][1] - nm0);
            sacc[nt][2] = __expf(sacc[nt][2] - nm1);
            sacc[nt][3] = __expf(sacc[nt][3] - nm1);
            ls0 += sacc[nt][0] + sacc[nt][1];
            ls1 += sacc[nt][2] + sacc[nt][3];
        }

        #pragma unroll
        for (int kt2 = 0; kt2 < 4; kt2++) {
            unsigned pfr[4];
            pfr[0] = h2u(__floats2half2_rn(sacc[2 * kt2][0],     sacc[2 * kt2][1]));
            pfr[1] = h2u(__floats2half2_rn(sacc[2 * kt2][2],     sacc[2 * kt2][3]));
            pfr[2] = h2u(__floats2half2_rn(sacc[2 * kt2 + 1][0], sacc[2 * kt2 + 1][1]));
            pfr[3] = h2u(__floats2half2_rn(sacc[2 * kt2 + 1][2], sacc[2 * kt2 + 1][3]));
            int vrow = kt2 * 16 + (l & 15);
            #pragma unroll
            for (int dv = 0; dv < 4; dv++) {
                int chunk = dv * 2 + (l >> 4);
                unsigned off = stg + 8192u + (unsigned)vrow * 128u +
                               (unsigned)((chunk ^ (vrow & 7)) << 4);
                unsigned vf4[4];
                ldsm4t(vf4, off);
                mma16816(oacc[2 * dv],     pfr, vf4);
                mma16816(oacc[2 * dv + 1], pfr, vf4 + 2);
            }
        }
        __syncthreads();
    }

    ls0 += __shfl_xor_sync(0xffffffffu, ls0, 1);
    ls0 += __shfl_xor_sync(0xffffffffu, ls0, 2);
    ls1 += __shfl_xor_sync(0xffffffffu, ls1, 1);
    ls1 += __shfl_xor_sync(0xffffffffu, ls1, 2);
    float inv0 = 1.0f / ls0, inv1 = 1.0f / ls1;
    __half* op0 = OutH + (size_t)qrow * 1024 + h * 64 + qcol;
    __half* op1 = OutH + (size_t)(qrow + 8) * 1024 + h * 64 + qcol;
    #pragma unroll
    for (int nt = 0; nt < 8; nt++) {
        *(unsigned*)(op0 + nt * 8) = h2u(__floats2half2_rn(oacc[nt][0] * inv0,
                                                           oacc[nt][1] * inv0));
        *(unsigned*)(op1 + nt * 8) = h2u(__floats2half2_rn(oacc[nt][2] * inv1,
                                                           oacc[nt][3] * inv1));
    }
}

// ---------------- host driver ----------------
extern "C" void kernel_launch(void* const* d_in, const int* in_sizes, int n_in,
                              void* d_out, int out_size) {
    (void)in_sizes; (void)n_in; (void)out_size;

    const int*   ids    = (const int*)  d_in[0];
    const float* memory = (const float*)d_in[1];
    const float* beacon = (const float*)d_in[2];
    const float* forget = (const float*)d_in[3];
    const float* embed  = (const float*)d_in[4];
    const float* ln1    = (const float*)d_in[5];
    const float* ln2    = (const float*)d_in[6];
    const float* Wsrc[12] = {
        (const float*)d_in[7],  (const float*)d_in[8],  (const float*)d_in[9],
        (const float*)d_in[10], (const float*)d_in[11], (const float*)d_in[12],
        (const float*)d_in[13], (const float*)d_in[14], (const float*)d_in[15],
        (const float*)d_in[16], (const float*)d_in[17], (const float*)d_in[18]
    };
    const float* Wg = (const float*)d_in[19];
    const float* Wu = (const float*)d_in[20];
    const float* Wd = (const float*)d_in[21];
    float* out = (float*)d_out;

    float* pool = nullptr;
    cudaGetSymbolAddress((void**)&pool, g_pool);
    __half* hp = nullptr;
    cudaGetSymbolAddress((void**)&hp, g_poolhf);

    float* cat  = pool + OFF_CAT;
    float* cosT = pool + OFF_COS;
    float* sinT = pool + OFF_SIN;
    __half* tqkv_h = (__half*)(pool + OFF_TQKV);
    __half* tsm_h  = tqkv_h + 3u * 1048576u;

    __half* xh = hp + B_XH;
    __half* ah = hp + B_AH;
    __half* yh = hp + B_YH;
    __half* gh = hp + B_GH;
    __half* mehAll = hp + B_MEH;
    __half* qh   = hp + HB_Q;
    __half* qbh  = hp + HB_QB;
    __half* qfh  = hp + HB_QF;
    __half* kbuf = hp + HB_K;
    __half* vbuf = hp + HB_V;
    __half* kf   = hp + HB_KF;
    __half* vf   = hp + HB_VF;

    cudaFuncSetAttribute(k_hmma,   cudaFuncAttributeMaxDynamicSharedMemorySize, SMEM_HM);
    cudaFuncSetAttribute(k_hmma64, cudaFuncAttributeMaxDynamicSharedMemorySize, SMEM_H64);
    cudaFuncSetAttribute(k_mlp,    cudaFuncAttributeMaxDynamicSharedMemorySize, SMEM_HM);

    const size_t WDD = (size_t)D * D;
    const size_t WDF = (size_t)D * F;
    const size_t WFD = (size_t)F * D;
    const size_t MDsz = (size_t)Mm * D;

    // ---- pre-loop ----
    k_tables<<<(1280 * 64 + 255) / 256, 256>>>(cosT, sinT);
    k_fillcat<<<(TOT * D + 255) / 256, 256>>>(cat, ids, embed, beacon, forget);
    {
        WcArgs wa;
        int off = 0;
        for (int i = 0; i < 12; i++) {
            wa.e[i] = { Wsrc[i], hp + BW_ALL + (size_t)i * 1048576, D, D, off, WDD };
            off += (D / 32) * (D / 32);
        }
        wa.e[12] = { Wg, hp + BW_ALL + 12582912, D, F, off, WDF }; off += (D/32)*(F/32);
        wa.e[13] = { Wu, hp + BW_ALL + 14680064, D, F, off, WDF }; off += (D/32)*(F/32);
        wa.e[14] = { Wd, hp + BW_ALL + 16777216, F, D, off, WFD }; off += (F/32)*(D/32);
        k_wconv<<<dim3(off, L), 256>>>(wa);
    }
    k_split<<<(L * Mm * D / 8 + 255) / 256, 256>>>(memory, mehAll, L * Mm * D);

    for (int l = 0; l < L; l++) {
        const float* mem_l = memory + (size_t)l * MDsz;
        __half* base_w = hp + BW_ALL + (size_t)l * WL_STRIDE;
        __half* wtH[15];
        for (int i = 0; i < 12; i++) wtH[i] = base_w + (size_t)i * 1048576;
        wtH[12] = base_w + 12582912;
        wtH[13] = base_w + 14680064;
        wtH[14] = base_w + 16777216;
        __half* meh = mehAll + (size_t)l * MDsz;

        k_rms<<<TOT + Mm, 256>>>(cat, ln1 + (size_t)l * D, xh,
                                 mem_l, out + (size_t)l * MDsz);

        // QKV + eight 128-row projections -> fp16 outputs
        {
            GArgs ga = {};
            for (int z = 0; z < 3; z++) {
                ga.Ah[z] = xh;
                ga.Bh[z] = wtH[z];
                ga.Ch[z] = tqkv_h + (size_t)z * 1048576;
                ga.mRows[z] = S;
            }
            const __half* bxh = xh + (size_t)S * D;
            const __half* fxh = xh + (size_t)(S + Mm) * D;
            const __half* sAh[8] = { meh, meh, bxh, bxh, bxh, fxh, fxh, fxh };
            int wmap[8] = {4, 5, 6, 7, 8, 9, 10, 11};
            for (int z = 0; z < 8; z++) {
                ga.Ah[3 + z] = sAh[z];
                ga.Bh[3 + z] = wtH[wmap[z]];
                ga.Ch[3 + z] = tsm_h + (size_t)z * 131072;
                ga.mRows[3 + z] = Mm;
            }
            k_hmma<<<dim3(8, 8, 11), 256, SMEM_HM>>>(ga, D, D, 0, 1);
        }
        // rope + reshape (fp16 in/out; Q scaled by 0.125)
        {
            RsArgs ra;
            ra.e[0]  = { tqkv_h,            qh,   S,  1024, 0,    Mm,   0.125f };
            ra.e[1]  = { tqkv_h + 1048576,  kbuf, S,  1280, 128,  Mm,   1.0f };
            ra.e[2]  = { tqkv_h + 2097152,  vbuf, S,  1280, 128,  -1,   1.0f };
            ra.e[3]  = { tsm_h,             kbuf, Mm, 1280, 0,    0,    1.0f };
            ra.e[4]  = { tsm_h + 131072,    vbuf, Mm, 1280, 0,    -1,   1.0f };
            ra.e[5]  = { tsm_h + 262144,    qbh,  Mm, 128,  0,    KHID, 0.125f };
            ra.e[6]  = { tsm_h + 393216,    kbuf, Mm, 1280, KHID, KHID, 1.0f };
            ra.e[7]  = { tsm_h + 524288,    vbuf, Mm, 1280, KHID, -1,   1.0f };
            ra.e[8]  = { tsm_h + 655360,    qfh,  Mm, 128,  0,    KHID, 0.125f };
            ra.e[9]  = { tsm_h + 786432,    kf,   Mm, 128,  0,    KHID, 1.0f };
            ra.e[10] = { tsm_h + 917504,    vf,   Mm, 128,  0,    -1,   1.0f };
            k_reshape<<<dim3(4096, 11), 256>>>(ra, cosT, sinT);
        }
        // attention
        {
            AtArgs aa;
            aa.Q[0] = qh;    aa.nq[0] = S;
            aa.K1[0] = kbuf; aa.V1[0] = vbuf; aa.len1[0] = KHID; aa.hs1[0] = 1280 * 64;
            aa.K2[0] = kf;   aa.V2[0] = vf;   aa.len2[0] = 0;    aa.hs2[0] = 128 * 64;
            aa.P[0] = Mm;    aa.OutH[0] = ah;
            aa.Q[1] = qbh;   aa.nq[1] = Mm;
            aa.K1[1] = kbuf; aa.V1[1] = vbuf; aa.len1[1] = TOT;  aa.hs1[1] = 1280 * 64;
            aa.K2[1] = kf;   aa.V2[1] = vf;   aa.len2[1] = 0;    aa.hs2[1] = 128 * 64;
            aa.P[1] = KHID;  aa.OutH[1] = ah + (size_t)S * D;
            aa.Q[2] = qfh;   aa.nq[2] = Mm;
            aa.K1[2] = kbuf; aa.V1[2] = vbuf; aa.len1[2] = KHID; aa.hs1[2] = 1280 * 64;
            aa.K2[2] = kf;   aa.V2[2] = vf;   aa.len2[2] = Mm;   aa.hs2[2] = 128 * 64;
            aa.P[2] = KHID;  aa.OutH[2] = ah + (size_t)KHID * D;
            k_attn<<<dim3(S / 64, H, 3), 128>>>(aa);
        }
        // Wo (+residual, f32) — narrow tiles for wave occupancy: grid 160
        k_hmma64<<<dim3(D / 64, TOT / 128), 256, SMEM_H64>>>(ah, wtH[3], cat, D, D, 1);
        k_rms<<<TOT, 256>>>(cat, ln2 + (size_t)l * D, yh, nullptr, nullptr);
        // fused MLP
        k_mlp<<<dim3(F / 64, TOT / 128), 256, SMEM_HM>>>(yh, wtH[12], wtH[13], gh, F, D);
        // down (+residual, f32) — narrow tiles: grid 160
        k_hmma64<<<dim3(D / 64, TOT / 128), 256, SMEM_H64>>>(gh, wtH[14], cat, D, F, 1);
    }
}

// round 14
// speedup vs baseline: 1.0448x; 1.0448x over previous
#include <cuda_runtime.h>
#include <cuda_fp16.h>
#include <math.h>

// Problem constants
constexpr int S  = 1024;
constexpr int Mm = 128;
constexpr int D  = 1024;
constexpr int H  = 16;
constexpr int HD = 64;
constexpr int F  = 2048;
constexpr int L  = 8;
constexpr int TOT = S + 2 * Mm;     // 1280
constexpr int KHID = Mm + S;        // 1152

// ---------------- f32 scratch pool ----------------
constexpr size_t OFF_CAT  = 0;                          // 1280*1024
constexpr size_t OFF_TQKV = 9437184;                    // reused as fp16 area
constexpr size_t OFF_COS  = 18874368;
constexpr size_t OFF_SIN  = 18956288;
constexpr size_t POOL_SZ  = 19038208;
__device__ __align__(16) float g_pool[POOL_SZ];

// ---------------- fp16 scratch pool ----------------
constexpr size_t WL_STRIDE = 18874368;   // per-layer: 12*1048576 + 3*2097152
constexpr size_t BW_ALL   = 0;           // 8 layers of converted weights
constexpr size_t B_XH     = 150994944;   // 1280*1024
constexpr size_t B_AH     = 152305664;
constexpr size_t B_YH     = 153616384;
constexpr size_t B_GH     = 154927104;   // 1280*2048
constexpr size_t B_MEH    = 157548544;   // 8 * 128*1024
constexpr size_t HB_Q     = 158597120;   // 16*1024*64
constexpr size_t HB_QB    = 159645696;   // 16*128*64
constexpr size_t HB_QF    = 159776768;
constexpr size_t HB_K     = 159907840;   // 16*1280*64
constexpr size_t HB_V     = 161218560;
constexpr size_t HB_KF    = 162529280;   // 16*128*64
constexpr size_t HB_VF    = 162660352;
constexpr size_t BPOOL_SZ = 162791424;
__device__ __align__(16) __half g_poolhf[BPOOL_SZ];

__device__ __forceinline__ unsigned h2u(__half2 h) { return *(unsigned*)&h; }

// ---------------- rope tables ----------------
__global__ void k_tables(float* cosT, float* sinT) {
    int idx = blockIdx.x * blockDim.x + threadIdx.x;
    if (idx >= 1280 * 64) return;
    int p = idx >> 6;
    int d = idx & 63;
    int i = d & 31;
    double inv = pow(10000.0, -((double)i) / 32.0);
    double ang = (double)p * inv;
    cosT[idx] = (float)cos(ang);
    sinT[idx] = (float)sin(ang);
}

// ---------------- initial residual ----------------
__global__ void k_fillcat(float* cat, const int* __restrict__ ids,
                          const float* __restrict__ embed,
                          const float* __restrict__ beacon,
                          const float* __restrict__ forget) {
    int idx = blockIdx.x * blockDim.x + threadIdx.x;
    if (idx >= TOT * D) return;
    int row = idx >> 10;
    int d = idx & 1023;
    float v;
    if (row < S)            v = embed[(size_t)ids[row] * D + d];
    else if (row < S + Mm)  v = beacon[(size_t)(row - S) * D + d];
    else                    v = forget[(size_t)(row - S - Mm) * D + d];
    cat[idx] = v;
}

// ---------------- rmsnorm -> fp16, fused gated-output ----------------
__global__ void k_rms(const float* __restrict__ in, const float* __restrict__ w,
                      __half* __restrict__ oh,
                      const float* __restrict__ mem, float* __restrict__ outg) {
    int row = blockIdx.x;
    int t = threadIdx.x;
    if (row >= TOT) {
        int idx = (row - TOT) * 1024 + t * 4;
        float4 bcn = *(const float4*)(in + (size_t)S * D + idx);
        float4 fgt = *(const float4*)(in + (size_t)(S + Mm) * D + idx);
        float4 mv  = *(const float4*)(mem + idx);
        float4 o;
        float g;
        g = 1.0f / (1.0f + expf(-fgt.x)); o.x = mv.x * g + bcn.x * (1.0f - g);
        g = 1.0f / (1.0f + expf(-fgt.y)); o.y = mv.y * g + bcn.y * (1.0f - g);
        g = 1.0f / (1.0f + expf(-fgt.z)); o.z = mv.z * g + bcn.z * (1.0f - g);
        g = 1.0f / (1.0f + expf(-fgt.w)); o.w = mv.w * g + bcn.w * (1.0f - g);
        *(float4*)(outg + idx) = o;
        return;
    }
    const float* r = in + (size_t)row * D;
    float4 v = *(const float4*)(r + t * 4);
    float ss = fmaf(v.x, v.x, fmaf(v.y, v.y, fmaf(v.z, v.z, v.w * v.w)));
    #pragma unroll
    for (int o = 16; o; o >>= 1) ss += __shfl_xor_sync(0xffffffffu, ss, o);
    __shared__ float wsum[8];
    __shared__ float sc;
    if ((t & 31) == 0) wsum[t >> 5] = ss;
    __syncthreads();
    if (t == 0) {
        float tot = 0.0f;
        #pragma unroll
        for (int i = 0; i < 8; i++) tot += wsum[i];
        sc = rsqrtf(tot / (float)D + 1e-5f);
    }
    __syncthreads();
    float scale = sc;
    float4 wv = *(const float4*)(w + t * 4);
    __half2 h01 = __floats2half2_rn(v.x * scale * wv.x, v.y * scale * wv.y);
    __half2 h23 = __floats2half2_rn(v.z * scale * wv.z, v.w * scale * wv.w);
    *(uint2*)(oh + (size_t)row * D + t * 4) = make_uint2(h2u(h01), h2u(h23));
}

// ---------------- weight transpose -> fp16, ALL layers ----------------
struct WcEnt { const float* src; __half* dh; int K; int N; int blkOff; size_t lsrc; };
struct WcArgs { WcEnt e[15]; };

__global__ void __launch_bounds__(256) k_wconv(WcArgs wa) {
    __shared__ float ts[32][33];
    int b = blockIdx.x;
    int lyr = blockIdx.y;
    int ei = 0;
    #pragma unroll
    for (int i = 14; i >= 1; i--) if (b >= wa.e[i].blkOff) { ei = i; break; }
    WcEnt E = wa.e[ei];
    const float* src = E.src + (size_t)lyr * E.lsrc;
    __half* dh = E.dh + (size_t)lyr * WL_STRIDE;
    int local = b - E.blkOff;
    int ntx = E.N >> 5;
    int tn = (local % ntx) << 5;
    int tk = (local / ntx) << 5;
    int t = threadIdx.x;
    {
        int row = t >> 3, c4 = (t & 7) << 2;
        float4 v = *(const float4*)(src + (size_t)(tk + row) * E.N + tn + c4);
        ts[row][c4 + 0] = v.x;
        ts[row][c4 + 1] = v.y;
        ts[row][c4 + 2] = v.z;
        ts[row][c4 + 3] = v.w;
    }
    __syncthreads();
    {
        int n = t >> 3, kq = (t & 7) << 2;
        __half2 h01 = __floats2half2_rn(ts[kq + 0][n], ts[kq + 1][n]);
        __half2 h23 = __floats2half2_rn(ts[kq + 2][n], ts[kq + 3][n]);
        *(uint2*)(dh + (size_t)(tn + n) * E.K + tk + kq) = make_uint2(h2u(h01), h2u(h23));
    }
}

// ---------------- plain f32 -> fp16 ----------------
__global__ void k_split(const float* __restrict__ src, __half* __restrict__ dh, int n) {
    int i = (blockIdx.x * 256 + threadIdx.x) * 8;
    if (i >= n) return;
    float4 a = *(const float4*)(src + i);
    float4 b = *(const float4*)(src + i + 4);
    uint4 o;
    o.x = h2u(__floats2half2_rn(a.x, a.y));
    o.y = h2u(__floats2half2_rn(a.z, a.w));
    o.z = h2u(__floats2half2_rn(b.x, b.y));
    o.w = h2u(__floats2half2_rn(b.z, b.w));
    *(uint4*)(dh + i) = o;
}

// ---------------- shared MMA helpers ----------------
__device__ __forceinline__ void mma16816(float* c, const unsigned* a, const unsigned* b) {
    asm volatile(
        "mma.sync.aligned.m16n8k16.row.col.f32.f16.f16.f32 "
        "{%0,%1,%2,%3}, {%4,%5,%6,%7}, {%8,%9}, {%0,%1,%2,%3};"
        : "+f"(c[0]), "+f"(c[1]), "+f"(c[2]), "+f"(c[3])
        : "r"(a[0]), "r"(a[1]), "r"(a[2]), "r"(a[3]), "r"(b[0]), "r"(b[1]));
}
__device__ __forceinline__ void ldsm4(unsigned* r, unsigned addr) {
    asm volatile("ldmatrix.sync.aligned.m8n8.x4.shared.b16 {%0,%1,%2,%3}, [%4];"
                 : "=r"(r[0]), "=r"(r[1]), "=r"(r[2]), "=r"(r[3]) : "r"(addr));
}
__device__ __forceinline__ void ldsm4t(unsigned* r, unsigned addr) {
    asm volatile("ldmatrix.sync.aligned.m8n8.x4.trans.shared.b16 {%0,%1,%2,%3}, [%4];"
                 : "=r"(r[0]), "=r"(r[1]), "=r"(r[2]), "=r"(r[3]) : "r"(addr));
}
__device__ __forceinline__ void cpasync16(unsigned saddr, const void* gptr) {
    asm volatile("cp.async.cg.shared.global [%0], [%1], 16;"
                 :: "r"(saddr), "l"(gptr) : "memory");
}
__device__ __forceinline__ void cp_commit() {
    asm volatile("cp.async.commit_group;" ::: "memory");
}
template<int NN> __device__ __forceinline__ void cp_wait() {
    asm volatile("cp.async.wait_group %0;" :: "n"(NN) : "memory");
}

// =======================================================================
// HMMA GEMM: C = A@B^T (+C). 128x128 tile, BK=64, 2-stage, 2 CTA/SM.
// outHalf: write fp16 to Ch instead of f32 C (accFlag must be 0).
// =======================================================================
struct GArgs {
    const __half* Ah[11];
    const __half* Bh[11];
    float* C[11];
    __half* Ch[11];
    int mRows[11];
};

constexpr int SMEM_HM = 65536;

__global__ void __launch_bounds__(256, 2) k_hmma(GArgs ga, int N, int K,
                                                 int accFlag, int outHalf) {
    extern __shared__ __align__(128) char smraw[];
    const int z = blockIdx.z;
    const int mbase = blockIdx.y << 7;
    if (mbase >= ga.mRows[z]) return;
    const int nbase = blockIdx.x << 7;

    const __half* Ah = ga.Ah[z];
    const __half* Bh = ga.Bh[z];

    const int t = threadIdx.x;
    const int l = t & 31;
    const int w = t >> 5;
    const int wr = w >> 2;
    const int wc = w & 3;
    const unsigned sb = (unsigned)__cvta_generic_to_shared(smraw);

    auto load_stage = [&](int c, int s) {
        unsigned stg = sb + (unsigned)s * 32768u;
        int k0 = c << 6;
        #pragma unroll
        for (int i = 0; i < 4; i++) {
            int id = t + i * 256;
            int row = id >> 3, kc = id & 7;
            unsigned soff = stg + (unsigned)row * 128u + (unsigned)((kc ^ (row & 7)) << 4);
            size_t ao = (size_t)(mbase + row) * K + k0 + kc * 8;
            size_t bo = (size_t)(nbase + row) * K + k0 + kc * 8;
            cpasync16(soff,          Ah + ao);
            cpasync16(soff + 16384u, Bh + bo);
        }
        cp_commit();
    };

    float acc[4][4][4];
    #pragma unroll
    for (int i = 0; i < 4; i++)
        #pragma unroll
        for (int j = 0; j < 4; j++)
            #pragma unroll
            for (int q = 0; q < 4; q++) acc[i][j][q] = 0.0f;

    const int nc = K >> 6;
    load_stage(0, 0);
    if (nc > 1) load_stage(1, 1);

    for (int c = 0; c < nc; c++) {
        if (c + 1 < nc) cp_wait<1>(); else cp_wait<0>();
        __syncthreads();
        unsigned stg = sb + (unsigned)(c & 1) * 32768u;
        #pragma unroll
        for (int ks = 0; ks < 4; ks++) {
            unsigned aH[4][4], bH[2][4];
            #pragma unroll
            for (int mt = 0; mt < 4; mt++) {
                int row = wr * 64 + mt * 16 + (l & 15);
                int chunk = ks * 2 + (l >> 4);
                unsigned off = stg + (unsigned)row * 128u + (unsigned)((chunk ^ (row & 7)) << 4);
                ldsm4(aH[mt], off);
            }
            #pragma unroll
            for (int p = 0; p < 2; p++) {
                int nrow = wc * 32 + p * 16 + ((l >> 1) & 8) + (l & 7);
                int chunk = ks * 2 + ((l >> 3) & 1);
                unsigned off = stg + 16384u + (unsigned)nrow * 128u +
                               (unsigned)((chunk ^ (nrow & 7)) << 4);
                ldsm4(bH[p], off);
            }
            #pragma unroll
            for (int mt = 0; mt < 4; mt++)
                #pragma unroll
                for (int j = 0; j < 4; j++)
                    mma16816(acc[mt][j], aH[mt], &bH[j >> 1][(j & 1) * 2]);
        }
        __syncthreads();
        if (c + 2 < nc) load_stage(c + 2, c & 1);
    }

    int r0 = wr * 64 + (l >> 2);
    int c0 = wc * 32 + (l & 3) * 2;
    if (outHalf) {
        __half* Ch = ga.Ch[z];
        #pragma unroll
        for (int mt = 0; mt < 4; mt++) {
            #pragma unroll
            for (int j = 0; j < 4; j++) {
                int row = mbase + r0 + mt * 16;
                int col = nbase + c0 + j * 8;
                *(unsigned*)(Ch + (size_t)row * N + col) =
                    h2u(__floats2half2_rn(acc[mt][j][0], acc[mt][j][1]));
                *(unsigned*)(Ch + (size_t)(row + 8) * N + col) =
                    h2u(__floats2half2_rn(acc[mt][j][2], acc[mt][j][3]));
            }
        }
    } else {
        float* C = ga.C[z];
        #pragma unroll
        for (int mt = 0; mt < 4; mt++) {
            #pragma unroll
            for (int j = 0; j < 4; j++) {
                int row = mbase + r0 + mt * 16;
                int col = nbase + c0 + j * 8;
                float2 v01 = { acc[mt][j][0], acc[mt][j][1] };
                float2 v23 = { acc[mt][j][2], acc[mt][j][3] };
                float* p0 = C + (size_t)row * N + col;
                float* p1 = C + (size_t)(row + 8) * N + col;
                if (accFlag) {
                    float2 o0 = *(const float2*)p0;
                    float2 o1 = *(const float2*)p1;
                    v01.x += o0.x; v01.y += o0.y;
                    v23.x += o1.x; v23.y += o1.y;
                }
                *(float2*)p0 = v01;
                *(float2*)p1 = v23;
            }
        }
    }
}

// =======================================================================
// Split-K HMMA GEMM: C += A@B^T partials via atomicAdd. 128x128 tile,
// BK=64, 2-stage, 2 CTA/SM. blockIdx.z selects the K-half.
// Residual must already be present in C.
// =======================================================================
__global__ void __launch_bounds__(256, 2) k_hmma_sk(const __half* __restrict__ Ah,
                                                    const __half* __restrict__ Bh,
                                                    float* __restrict__ C,
                                                    int N, int K, int ksplit) {
    extern __shared__ __align__(128) char smraw[];
    const int mbase = blockIdx.y << 7;
    const int nbase = blockIdx.x << 7;
    const int kseg = K / ksplit;
    const int kofs = blockIdx.z * kseg;

    const int t = threadIdx.x;
    const int l = t & 31;
    const int w = t >> 5;
    const int wr = w >> 2;
    const int wc = w & 3;
    const unsigned sb = (unsigned)__cvta_generic_to_shared(smraw);

    auto load_stage = [&](int c, int s) {
        unsigned stg = sb + (unsigned)s * 32768u;
        int k0 = kofs + (c << 6);
        #pragma unroll
        for (int i = 0; i < 4; i++) {
            int id = t + i * 256;
            int row = id >> 3, kc = id & 7;
            unsigned soff = stg + (unsigned)row * 128u + (unsigned)((kc ^ (row & 7)) << 4);
            size_t ao = (size_t)(mbase + row) * K + k0 + kc * 8;
            size_t bo = (size_t)(nbase + row) * K + k0 + kc * 8;
            cpasync16(soff,          Ah + ao);
            cpasync16(soff + 16384u, Bh + bo);
        }
        cp_commit();
    };

    float acc[4][4][4];
    #pragma unroll
    for (int i = 0; i < 4; i++)
        #pragma unroll
        for (int j = 0; j < 4; j++)
            #pragma unroll
            for (int q = 0; q < 4; q++) acc[i][j][q] = 0.0f;

    const int nc = kseg >> 6;
    load_stage(0, 0);
    if (nc > 1) load_stage(1, 1);

    for (int c = 0; c < nc; c++) {
        if (c + 1 < nc) cp_wait<1>(); else cp_wait<0>();
        __syncthreads();
        unsigned stg = sb + (unsigned)(c & 1) * 32768u;
        #pragma unroll
        for (int ks = 0; ks < 4; ks++) {
            unsigned aH[4][4], bH[2][4];
            #pragma unroll
            for (int mt = 0; mt < 4; mt++) {
                int row = wr * 64 + mt * 16 + (l & 15);
                int chunk = ks * 2 + (l >> 4);
                unsigned off = stg + (unsigned)row * 128u + (unsigned)((chunk ^ (row & 7)) << 4);
                ldsm4(aH[mt], off);
            }
            #pragma unroll
            for (int p = 0; p < 2; p++) {
                int nrow = wc * 32 + p * 16 + ((l >> 1) & 8) + (l & 7);
                int chunk = ks * 2 + ((l >> 3) & 1);
                unsigned off = stg + 16384u + (unsigned)nrow * 128u +
                               (unsigned)((chunk ^ (nrow & 7)) << 4);
                ldsm4(bH[p], off);
            }
            #pragma unroll
            for (int mt = 0; mt < 4; mt++)
                #pragma unroll
                for (int j = 0; j < 4; j++)
                    mma16816(acc[mt][j], aH[mt], &bH[j >> 1][(j & 1) * 2]);
        }
        __syncthreads();
        if (c + 2 < nc) load_stage(c + 2, c & 1);
    }

    int r0 = wr * 64 + (l >> 2);
    int c0 = wc * 32 + (l & 3) * 2;
    #pragma unroll
    for (int mt = 0; mt < 4; mt++) {
        #pragma unroll
        for (int j = 0; j < 4; j++) {
            int row = mbase + r0 + mt * 16;
            int col = nbase + c0 + j * 8;
            float* p0 = C + (size_t)row * N + col;
            float* p1 = C + (size_t)(row + 8) * N + col;
            atomicAdd(p0,     acc[mt][j][0]);
            atomicAdd(p0 + 1, acc[mt][j][1]);
            atomicAdd(p1,     acc[mt][j][2]);
            atomicAdd(p1 + 1, acc[mt][j][3]);
        }
    }
}

// =======================================================================
// Fused MLP: gh = silu(A@Bg^T) * (A@Bu^T), fp16 out. 128x64 tile.
// =======================================================================
__global__ void __launch_bounds__(256, 2) k_mlp(const __half* __restrict__ A,
                                                const __half* __restrict__ Bg,
                                                const __half* __restrict__ Bu,
                                                __half* __restrict__ Cg,
                                                int N, int K) {
    extern __shared__ __align__(128) char smraw[];
    const int mbase = blockIdx.y << 7;
    const int nbase = blockIdx.x << 6;

    const int t = threadIdx.x;
    const int l = t & 31;
    const int w = t >> 5;
    const int wr = w >> 2;
    const int wc = w & 3;
    const unsigned sb = (unsigned)__cvta_generic_to_shared(smraw);

    auto load_stage = [&](int c, int s) {
        unsigned stg = sb + (unsigned)s * 32768u;
        int k0 = c << 6;
        #pragma unroll
        for (int i = 0; i < 4; i++) {
            int id = t + i * 256;
            int row = id >> 3, kc = id & 7;
            unsigned soff = stg + (unsigned)row * 128u + (unsigned)((kc ^ (row & 7)) << 4);
            cpasync16(soff, A + (size_t)(mbase + row) * K + k0 + kc * 8);
        }
        #pragma unroll
        for (int i = 0; i < 2; i++) {
            int id = t + i * 256;
            int row = id >> 3, kc = id & 7;
            unsigned soff = stg + 16384u + (unsigned)row * 128u +
                            (unsigned)((kc ^ (row & 7)) << 4);
            size_t bo = (size_t)(nbase + row) * K + k0 + kc * 8;
            cpasync16(soff,         Bg + bo);
            cpasync16(soff + 8192u, Bu + bo);
        }
        cp_commit();
    };

    float ag[4][2][4], au[4][2][4];
    #pragma unroll
    for (int i = 0; i < 4; i++)
        #pragma unroll
        for (int j = 0; j < 2; j++)
            #pragma unroll
            for (int q = 0; q < 4; q++) { ag[i][j][q] = 0.0f; au[i][j][q] = 0.0f; }

    const int nc = K >> 6;
    load_stage(0, 0);
    load_stage(1, 1);

    for (int c = 0; c < nc; c++) {
        if (c + 1 < nc) cp_wait<1>(); else cp_wait<0>();
        __syncthreads();
        unsigned stg = sb + (unsigned)(c & 1) * 32768u;
        #pragma unroll
        for (int ks = 0; ks < 4; ks++) {
            unsigned aH[4][4], bG[4], bU[4];
            #pragma unroll
            for (int mt = 0; mt < 4; mt++) {
                int row = wr * 64 + mt * 16 + (l & 15);
                int chunk = ks * 2 + (l >> 4);
                unsigned off = stg + (unsigned)row * 128u + (unsigned)((chunk ^ (row & 7)) << 4);
                ldsm4(aH[mt], off);
            }
            {
                int nrow = wc * 16 + ((l >> 1) & 8) + (l & 7);
                int chunk = ks * 2 + ((l >> 3) & 1);
                unsigned off = stg + 16384u + (unsigned)nrow * 128u +
                               (unsigned)((chunk ^ (nrow & 7)) << 4);
                ldsm4(bG, off);
                ldsm4(bU, off + 8192u);
            }
            #pragma unroll
            for (int mt = 0; mt < 4; mt++)
                #pragma unroll
                for (int j = 0; j < 2; j++) {
                    mma16816(ag[mt][j], aH[mt], &bG[j * 2]);
                    mma16816(au[mt][j], aH[mt], &bU[j * 2]);
                }
        }
        __syncthreads();
        if (c + 2 < nc) load_stage(c + 2, c & 1);
    }

    int r0 = wr * 64 + (l >> 2);
    int c0 = wc * 16 + (l & 3) * 2;
    #pragma unroll
    for (int mt = 0; mt < 4; mt++) {
        #pragma unroll
        for (int j = 0; j < 2; j++) {
            int row = mbase + r0 + mt * 16;
            int col = nbase + c0 + j * 8;
            float g0 = ag[mt][j][0], g1 = ag[mt][j][1];
            float g2 = ag[mt][j][2], g3 = ag[mt][j][3];
            float v0 = g0 / (1.0f + expf(-g0)) * au[mt][j][0];
            float v1 = g1 / (1.0f + expf(-g1)) * au[mt][j][1];
            float v2 = g2 / (1.0f + expf(-g2)) * au[mt][j][2];
            float v3 = g3 / (1.0f + expf(-g3)) * au[mt][j][3];
            *(unsigned*)(Cg + (size_t)row * N + col)       = h2u(__floats2half2_rn(v0, v1));
            *(unsigned*)(Cg + (size_t)(row + 8) * N + col) = h2u(__floats2half2_rn(v2, v3));
        }
    }
}

// ---------------- rope + head-major reshape (fp16 in -> fp16 out) ----------------
struct RsOne {
    const __half* src;
    __half*       dst;
    int rows;
    int dstStride;
    int dstOff;
    int posBase;
    float scl;
};
struct RsArgs { RsOne e[11]; };

__global__ void k_reshape(RsArgs ra, const float* __restrict__ cosT,
                          const float* __restrict__ sinT) {
    RsOne a = ra.e[blockIdx.y];
    int idx = blockIdx.x * 256 + threadIdx.x;
    if (idx >= a.rows * 1024) return;
    int row = idx >> 10;
    int n = idx & 1023;
    int h = n >> 6;
    int d = n & 63;
    float v = __half2float(a.src[idx]);
    float o;
    if (a.posBase >= 0) {
        int pos = a.posBase + row;
        float partner = (d < 32)
            ? -__half2float(a.src[(size_t)row * 1024 + h * 64 + d + 32])
            :  __half2float(a.src[(size_t)row * 1024 + h * 64 + d - 32]);
        o = v * cosT[pos * 64 + d] + partner * sinT[pos * 64 + d];
    } else {
        o = v;
    }
    a.dst[((size_t)h * a.dstStride + a.dstOff + row) * 64 + d] = __float2half_rn(o * a.scl);
}

// ---------------- HMMA flash attention, z-batched, double-buffered K/V ----------------
struct AtArgs {
    const __half* Q[3];  int nq[3];
    const __half* K1[3]; const __half* V1[3]; int len1[3]; int hs1[3];
    const __half* K2[3]; const __half* V2[3]; int len2[3]; int hs2[3];
    int P[3]; __half* OutH[3];
};

__global__ void __launch_bounds__(128) k_attn(AtArgs aa) {
    const int z = blockIdx.z;
    const int qb = blockIdx.x * 64;
    if (qb >= aa.nq[z]) return;
    const int nq = aa.nq[z], len1 = aa.len1[z], hs1 = aa.hs1[z];
    const int len2 = aa.len2[z], hs2 = aa.hs2[z], P = aa.P[z];
    const __half* K1 = aa.K1[z]; const __half* V1 = aa.V1[z];
    const __half* K2 = aa.K2[z]; const __half* V2 = aa.V2[z];
    __half* OutH = aa.OutH[z];

    const int h = blockIdx.y;
    const int t = threadIdx.x;
    const int l = t & 31;
    const int w = t >> 5;

    __shared__ __align__(16) __half sm[16384];
    const unsigned sb = (unsigned)__cvta_generic_to_shared(sm);

    const __half* Qh = aa.Q[z] + (size_t)h * nq * 64;
    const int qrow = qb + w * 16 + (l >> 2);
    const int qcol = (l & 3) * 2;
    unsigned qfr[4][4];
    #pragma unroll
    for (int dt = 0; dt < 4; dt++) {
        qfr[dt][0] = *(const unsigned*)(Qh + (size_t)qrow * 64 + dt * 16 + qcol);
        qfr[dt][1] = *(const unsigned*)(Qh + (size_t)(qrow + 8) * 64 + dt * 16 + qcol);
        qfr[dt][2] = *(const unsigned*)(Qh + (size_t)qrow * 64 + dt * 16 + 8 + qcol);
        qfr[dt][3] = *(const unsigned*)(Qh + (size_t)(qrow + 8) * 64 + dt * 16 + 8 + qcol);
    }

    float oacc[8][4];
    #pragma unroll
    for (int i = 0; i < 8; i++)
        #pragma unroll
        for (int q = 0; q < 4; q++) oacc[i][q] = 0.0f;
    float m0 = -1e30f, m1 = -1e30f, ls0 = 0.0f, ls1 = 0.0f;

    const int total = len1 + len2;
    const int eff = min(total, P + qb + 64);
    const int ntk = (eff + 63) >> 6;
    const int wqmin = qb + w * 16;

    auto load_kv = [&](int kt, int s) {
        #pragma unroll
        for (int i = 0; i < 4; i++) {
            int id = t + i * 128;
            int row = id >> 3, kc = id & 7;
            int j = kt * 64 + row;
            const __half *kp, *vp;
            if (j < len1) {
                kp = K1 + (size_t)h * hs1 + (size_t)j * 64;
                vp = V1 + (size_t)h * hs1 + (size_t)j * 64;
            } else {
                kp = K2 + (size_t)h * hs2 + (size_t)(j - len1) * 64;
                vp = V2 + (size_t)h * hs2 + (size_t)(j - len1) * 64;
            }
            unsigned soff = sb + (unsigned)s * 16384u + (unsigned)row * 128u +
                            (unsigned)((kc ^ (row & 7)) << 4);
            cpasync16(soff,         kp + kc * 8);
            cpasync16(soff + 8192u, vp + kc * 8);
        }
        cp_commit();
    };

    load_kv(0, 0);

    for (int kt = 0; kt < ntk; kt++) {
        if (kt + 1 < ntk) { load_kv(kt + 1, (kt + 1) & 1); cp_wait<1>(); }
        else cp_wait<0>();
        __syncthreads();
        unsigned stg = sb + (unsigned)(kt & 1) * 16384u;

        float sacc[8][4];
        #pragma unroll
        for (int i = 0; i < 8; i++)
            #pragma unroll
            for (int q = 0; q < 4; q++) sacc[i][q] = 0.0f;
        #pragma unroll
        for (int p = 0; p < 4; p++) {
            int nrow = p * 16 + ((l >> 1) & 8) + (l & 7);
            #pragma unroll
            for (int dt = 0; dt < 4; dt++) {
                int chunk = dt * 2 + ((l >> 3) & 1);
                unsigned off = stg + (unsigned)nrow * 128u + (unsigned)((chunk ^ (nrow & 7)) << 4);
                unsigned kfr[4];
                ldsm4(kfr, off);
                mma16816(sacc[2 * p],     qfr[dt], kfr);
                mma16816(sacc[2 * p + 1], qfr[dt], kfr + 2);
            }
        }

        int kg0 = kt * 64;
        if (!(kg0 + 63 < P || kg0 + 63 - P <= wqmin)) {
            #pragma unroll
            for (int nt = 0; nt < 8; nt++) {
                int col = kg0 + nt * 8 + qcol;
                if (!(col < P || col - P <= qrow))         sacc[nt][0] = -1e30f;
                if (!(col + 1 < P || col + 1 - P <= qrow)) sacc[nt][1] = -1e30f;
                if (!(col < P || col - P <= qrow + 8))         sacc[nt][2] = -1e30f;
                if (!(col + 1 < P || col + 1 - P <= qrow + 8)) sacc[nt][3] = -1e30f;
            }
        }

        float tm0 = -1e30f, tm1 = -1e30f;
        #pragma unroll
        for (int nt = 0; nt < 8; nt++) {
            tm0 = fmaxf(tm0, fmaxf(sacc[nt][0], sacc[nt][1]));
            tm1 = fmaxf(tm1, fmaxf(sacc[nt][2], sacc[nt][3]));
        }
        tm0 = fmaxf(tm0, __shfl_xor_sync(0xffffffffu, tm0, 1));
        tm0 = fmaxf(tm0, __shfl_xor_sync(0xffffffffu, tm0, 2));
        tm1 = fmaxf(tm1, __shfl_xor_sync(0xffffffffu, tm1, 1));
        tm1 = fmaxf(tm1, __shfl_xor_sync(0xffffffffu, tm1, 2));
        float nm0 = fmaxf(m0, tm0), nm1 = fmaxf(m1, tm1);
        float cr0 = __expf(m0 - nm0), cr1 = __expf(m1 - nm1);
        ls0 *= cr0; ls1 *= cr1;
        #pragma unroll
        for (int nt = 0; nt < 8; nt++) {
            oacc[nt][0] *= cr0; oacc[nt][1] *= cr0;
            oacc[nt][2] *= cr1; oacc[nt][3] *= cr1;
        }
        m0 = nm0; m1 = nm1;
        #pragma unroll
        for (int nt = 0; nt < 8; nt++) {
            sacc[nt][0] = __expf(sacc[nt][0] - nm0);
            sacc[nt][1] = __expf(sacc[nt][1] - nm0);
            sacc[nt][2] = __expf(sacc[nt][2] - nm1);
            sacc[nt][3] = __expf(sacc[nt][3] - nm1);
            ls0 += sacc[nt][0] + sacc[nt][1];
            ls1 += sacc[nt][2] + sacc[nt][3];
        }

        #pragma unroll
        for (int kt2 = 0; kt2 < 4; kt2++) {
            unsigned pfr[4];
            pfr[0] = h2u(__floats2half2_rn(sacc[2 * kt2][0],     sacc[2 * kt2][1]));
            pfr[1] = h2u(__floats2half2_rn(sacc[2 * kt2][2],     sacc[2 * kt2][3]));
            pfr[2] = h2u(__floats2half2_rn(sacc[2 * kt2 + 1][0], sacc[2 * kt2 + 1][1]));
            pfr[3] = h2u(__floats2half2_rn(sacc[2 * kt2 + 1][2], sacc[2 * kt2 + 1][3]));
            int vrow = kt2 * 16 + (l & 15);
            #pragma unroll
            for (int dv = 0; dv < 4; dv++) {
                int chunk = dv * 2 + (l >> 4);
                unsigned off = stg + 8192u + (unsigned)vrow * 128u +
                               (unsigned)((chunk ^ (vrow & 7)) << 4);
                unsigned vf4[4];
                ldsm4t(vf4, off);
                mma16816(oacc[2 * dv],     pfr, vf4);
                mma16816(oacc[2 * dv + 1], pfr, vf4 + 2);
            }
        }
        __syncthreads();
    }

    ls0 += __shfl_xor_sync(0xffffffffu, ls0, 1);
    ls0 += __shfl_xor_sync(0xffffffffu, ls0, 2);
    ls1 += __shfl_xor_sync(0xffffffffu, ls1, 1);
    ls1 += __shfl_xor_sync(0xffffffffu, ls1, 2);
    float inv0 = 1.0f / ls0, inv1 = 1.0f / ls1;
    __half* op0 = OutH + (size_t)qrow * 1024 + h * 64 + qcol;
    __half* op1 = OutH + (size_t)(qrow + 8) * 1024 + h * 64 + qcol;
    #pragma unroll
    for (int nt = 0; nt < 8; nt++) {
        *(unsigned*)(op0 + nt * 8) = h2u(__floats2half2_rn(oacc[nt][0] * inv0,
                                                           oacc[nt][1] * inv0));
        *(unsigned*)(op1 + nt * 8) = h2u(__floats2half2_rn(oacc[nt][2] * inv1,
                                                           oacc[nt][3] * inv1));
    }
}

// ---------------- host driver ----------------
extern "C" void kernel_launch(void* const* d_in, const int* in_sizes, int n_in,
                              void* d_out, int out_size) {
    (void)in_sizes; (void)n_in; (void)out_size;

    const int*   ids    = (const int*)  d_in[0];
    const float* memory = (const float*)d_in[1];
    const float* beacon = (const float*)d_in[2];
    const float* forget = (const float*)d_in[3];
    const float* embed  = (const float*)d_in[4];
    const float* ln1    = (const float*)d_in[5];
    const float* ln2    = (const float*)d_in[6];
    const float* Wsrc[12] = {
        (const float*)d_in[7],  (const float*)d_in[8],  (const float*)d_in[9],
        (const float*)d_in[10], (const float*)d_in[11], (const float*)d_in[12],
        (const float*)d_in[13], (const float*)d_in[14], (const float*)d_in[15],
        (const float*)d_in[16], (const float*)d_in[17], (const float*)d_in[18]
    };
    const float* Wg = (const float*)d_in[19];
    const float* Wu = (const float*)d_in[20];
    const float* Wd = (const float*)d_in[21];
    float* out = (float*)d_out;

    float* pool = nullptr;
    cudaGetSymbolAddress((void**)&pool, g_pool);
    __half* hp = nullptr;
    cudaGetSymbolAddress((void**)&hp, g_poolhf);

    float* cat  = pool + OFF_CAT;
    float* cosT = pool + OFF_COS;
    float* sinT = pool + OFF_SIN;
    __half* tqkv_h = (__half*)(pool + OFF_TQKV);
    __half* tsm_h  = tqkv_h + 3u * 1048576u;

    __half* xh = hp + B_XH;
    __half* ah = hp + B_AH;
    __half* yh = hp + B_YH;
    __half* gh = hp + B_GH;
    __half* mehAll = hp + B_MEH;
    __half* qh   = hp + HB_Q;
    __half* qbh  = hp + HB_QB;
    __half* qfh  = hp + HB_QF;
    __half* kbuf = hp + HB_K;
    __half* vbuf = hp + HB_V;
    __half* kf   = hp + HB_KF;
    __half* vf   = hp + HB_VF;

    cudaFuncSetAttribute(k_hmma,    cudaFuncAttributeMaxDynamicSharedMemorySize, SMEM_HM);
    cudaFuncSetAttribute(k_hmma_sk, cudaFuncAttributeMaxDynamicSharedMemorySize, SMEM_HM);
    cudaFuncSetAttribute(k_mlp,     cudaFuncAttributeMaxDynamicSharedMemorySize, SMEM_HM);

    const size_t WDD = (size_t)D * D;
    const size_t WDF = (size_t)D * F;
    const size_t WFD = (size_t)F * D;
    const size_t MDsz = (size_t)Mm * D;

    // ---- pre-loop ----
    k_tables<<<(1280 * 64 + 255) / 256, 256>>>(cosT, sinT);
    k_fillcat<<<(TOT * D + 255) / 256, 256>>>(cat, ids, embed, beacon, forget);
    {
        WcArgs wa;
        int off = 0;
        for (int i = 0; i < 12; i++) {
            wa.e[i] = { Wsrc[i], hp + BW_ALL + (size_t)i * 1048576, D, D, off, WDD };
            off += (D / 32) * (D / 32);
        }
        wa.e[12] = { Wg, hp + BW_ALL + 12582912, D, F, off, WDF }; off += (D/32)*(F/32);
        wa.e[13] = { Wu, hp + BW_ALL + 14680064, D, F, off, WDF }; off += (D/32)*(F/32);
        wa.e[14] = { Wd, hp + BW_ALL + 16777216, F, D, off, WFD }; off += (F/32)*(D/32);
        k_wconv<<<dim3(off, L), 256>>>(wa);
    }
    k_split<<<(L * Mm * D / 8 + 255) / 256, 256>>>(memory, mehAll, L * Mm * D);

    for (int l = 0; l < L; l++) {
        const float* mem_l = memory + (size_t)l * MDsz;
        __half* base_w = hp + BW_ALL + (size_t)l * WL_STRIDE;
        __half* wtH[15];
        for (int i = 0; i < 12; i++) wtH[i] = base_w + (size_t)i * 1048576;
        wtH[12] = base_w + 12582912;
        wtH[13] = base_w + 14680064;
        wtH[14] = base_w + 16777216;
        __half* meh = mehAll + (size_t)l * MDsz;

        k_rms<<<TOT + Mm, 256>>>(cat, ln1 + (size_t)l * D, xh,
                                 mem_l, out + (size_t)l * MDsz);

        // QKV + eight 128-row projections -> fp16 outputs
        {
            GArgs ga = {};
            for (int z = 0; z < 3; z++) {
                ga.Ah[z] = xh;
                ga.Bh[z] = wtH[z];
                ga.Ch[z] = tqkv_h + (size_t)z * 1048576;
                ga.mRows[z] = S;
            }
            const __half* bxh = xh + (size_t)S * D;
            const __half* fxh = xh + (size_t)(S + Mm) * D;
            const __half* sAh[8] = { meh, meh, bxh, bxh, bxh, fxh, fxh, fxh };
            int wmap[8] = {4, 5, 6, 7, 8, 9, 10, 11};
            for (int z = 0; z < 8; z++) {
                ga.Ah[3 + z] = sAh[z];
                ga.Bh[3 + z] = wtH[wmap[z]];
                ga.Ch[3 + z] = tsm_h + (size_t)z * 131072;
                ga.mRows[3 + z] = Mm;
            }
            k_hmma<<<dim3(8, 8, 11), 256, SMEM_HM>>>(ga, D, D, 0, 1);
        }
        // rope + reshape (fp16 in/out; Q scaled by 0.125)
        {
            RsArgs ra;
            ra.e[0]  = { tqkv_h,            qh,   S,  1024, 0,    Mm,   0.125f };
            ra.e[1]  = { tqkv_h + 1048576,  kbuf, S,  1280, 128,  Mm,   1.0f };
            ra.e[2]  = { tqkv_h + 2097152,  vbuf, S,  1280, 128,  -1,   1.0f };
            ra.e[3]  = { tsm_h,             kbuf, Mm, 1280, 0,    0,    1.0f };
            ra.e[4]  = { tsm_h + 131072,    vbuf, Mm, 1280, 0,    -1,   1.0f };
            ra.e[5]  = { tsm_h + 262144,    qbh,  Mm, 128,  0,    KHID, 0.125f };
            ra.e[6]  = { tsm_h + 393216,    kbuf, Mm, 1280, KHID, KHID, 1.0f };
            ra.e[7]  = { tsm_h + 524288,    vbuf, Mm, 1280, KHID, -1,   1.0f };
            ra.e[8]  = { tsm_h + 655360,    qfh,  Mm, 128,  0,    KHID, 0.125f };
            ra.e[9]  = { tsm_h + 786432,    kf,   Mm, 128,  0,    KHID, 1.0f };
            ra.e[10] = { tsm_h + 917504,    vf,   Mm, 128,  0,    -1,   1.0f };
            k_reshape<<<dim3(4096, 11), 256>>>(ra, cosT, sinT);
        }
        // attention
        {
            AtArgs aa;
            aa.Q[0] = qh;    aa.nq[0] = S;
            aa.K1[0] = kbuf; aa.V1[0] = vbuf; aa.len1[0] = KHID; aa.hs1[0] = 1280 * 64;
            aa.K2[0] = kf;   aa.V2[0] = vf;   aa.len2[0] = 0;    aa.hs2[0] = 128 * 64;
            aa.P[0] = Mm;    aa.OutH[0] = ah;
            aa.Q[1] = qbh;   aa.nq[1] = Mm;
            aa.K1[1] = kbuf; aa.V1[1] = vbuf; aa.len1[1] = TOT;  aa.hs1[1] = 1280 * 64;
            aa.K2[1] = kf;   aa.V2[1] = vf;   aa.len2[1] = 0;    aa.hs2[1] = 128 * 64;
            aa.P[1] = KHID;  aa.OutH[1] = ah + (size_t)S * D;
            aa.Q[2] = qfh;   aa.nq[2] = Mm;
            aa.K1[2] = kbuf; aa.V1[2] = vbuf; aa.len1[2] = KHID; aa.hs1[2] = 1280 * 64;
            aa.K2[2] = kf;   aa.V2[2] = vf;   aa.len2[2] = Mm;   aa.hs2[2] = 128 * 64;
            aa.P[2] = KHID;  aa.OutH[2] = ah + (size_t)KHID * D;
            k_attn<<<dim3(S / 64, H, 3), 128>>>(aa);
        }
        // Wo (+residual already in cat) — split-K=2: 160 CTAs, half-length K loops
        k_hmma_sk<<<dim3(8, 10, 2), 256, SMEM_HM>>>(ah, wtH[3], cat, D, D, 2);
        k_rms<<<TOT, 256>>>(cat, ln2 + (size_t)l * D, yh, nullptr, nullptr);
        // fused MLP
        k_mlp<<<dim3(F / 64, TOT / 128), 256, SMEM_HM>>>(yh, wtH[12], wtH[13], gh, F, D);
        // down (+residual already in cat) — split-K=2
        k_hmma_sk<<<dim3(8, 10, 2), 256, SMEM_HM>>>(gh, wtH[14], cat, D, F, 2);
    }
}

// round 15
// speedup vs baseline: 1.1701x; 1.1199x over previous
#include <cuda_runtime.h>
#include <cuda_fp16.h>
#include <math.h>

// Problem constants
constexpr int S  = 1024;
constexpr int Mm = 128;
constexpr int D  = 1024;
constexpr int H  = 16;
constexpr int HD = 64;
constexpr int F  = 2048;
constexpr int L  = 8;
constexpr int TOT = S + 2 * Mm;     // 1280
constexpr int KHID = Mm + S;        // 1152

// ---------------- f32 scratch pool ----------------
constexpr size_t OFF_CAT  = 0;                          // 1280*1024
constexpr size_t OFF_TQKV = 9437184;                    // reused as fp16 area
constexpr size_t OFF_COS  = 18874368;
constexpr size_t OFF_SIN  = 18956288;
constexpr size_t POOL_SZ  = 19038208;
__device__ __align__(16) float g_pool[POOL_SZ];

// ---------------- fp16 scratch pool ----------------
constexpr size_t WL_STRIDE = 18874368;   // per-layer: 12*1048576 + 3*2097152
constexpr size_t BW_ALL   = 0;           // 8 layers of converted weights
constexpr size_t B_XH     = 150994944;   // 1280*1024
constexpr size_t B_AH     = 152305664;
constexpr size_t B_YH     = 153616384;
constexpr size_t B_GH     = 154927104;   // 1280*2048
constexpr size_t B_MEH    = 157548544;   // 8 * 128*1024
constexpr size_t HB_Q     = 158597120;   // 16*1024*64
constexpr size_t HB_QB    = 159645696;   // 16*128*64
constexpr size_t HB_QF    = 159776768;
constexpr size_t HB_K     = 159907840;   // 16*1280*64
constexpr size_t HB_V     = 161218560;
constexpr size_t HB_KF    = 162529280;   // 16*128*64
constexpr size_t HB_VF    = 162660352;
constexpr size_t BPOOL_SZ = 162791424;
__device__ __align__(16) __half g_poolhf[BPOOL_SZ];

__device__ __forceinline__ unsigned h2u(__half2 h) { return *(unsigned*)&h; }

// ---------------- rope tables ----------------
__global__ void k_tables(float* cosT, float* sinT) {
    int idx = blockIdx.x * blockDim.x + threadIdx.x;
    if (idx >= 1280 * 64) return;
    int p = idx >> 6;
    int d = idx & 63;
    int i = d & 31;
    double inv = pow(10000.0, -((double)i) / 32.0);
    double ang = (double)p * inv;
    cosT[idx] = (float)cos(ang);
    sinT[idx] = (float)sin(ang);
}

// ---------------- initial residual ----------------
__global__ void k_fillcat(float* cat, const int* __restrict__ ids,
                          const float* __restrict__ embed,
                          const float* __restrict__ beacon,
                          const float* __restrict__ forget) {
    int idx = blockIdx.x * blockDim.x + threadIdx.x;
    if (idx >= TOT * D) return;
    int row = idx >> 10;
    int d = idx & 1023;
    float v;
    if (row < S)            v = embed[(size_t)ids[row] * D + d];
    else if (row < S + Mm)  v = beacon[(size_t)(row - S) * D + d];
    else                    v = forget[(size_t)(row - S - Mm) * D + d];
    cat[idx] = v;
}

// ---------------- rmsnorm -> fp16, fused gated-output ----------------
__global__ void k_rms(const float* __restrict__ in, const float* __restrict__ w,
                      __half* __restrict__ oh,
                      const float* __restrict__ mem, float* __restrict__ outg) {
    int row = blockIdx.x;
    int t = threadIdx.x;
    if (row >= TOT) {
        int idx = (row - TOT) * 1024 + t * 4;
        float4 bcn = *(const float4*)(in + (size_t)S * D + idx);
        float4 fgt = *(const float4*)(in + (size_t)(S + Mm) * D + idx);
        float4 mv  = *(const float4*)(mem + idx);
        float4 o;
        float g;
        g = 1.0f / (1.0f + expf(-fgt.x)); o.x = mv.x * g + bcn.x * (1.0f - g);
        g = 1.0f / (1.0f + expf(-fgt.y)); o.y = mv.y * g + bcn.y * (1.0f - g);
        g = 1.0f / (1.0f + expf(-fgt.z)); o.z = mv.z * g + bcn.z * (1.0f - g);
        g = 1.0f / (1.0f + expf(-fgt.w)); o.w = mv.w * g + bcn.w * (1.0f - g);
        *(float4*)(outg + idx) = o;
        return;
    }
    const float* r = in + (size_t)row * D;
    float4 v = *(const float4*)(r + t * 4);
    float ss = fmaf(v.x, v.x, fmaf(v.y, v.y, fmaf(v.z, v.z, v.w * v.w)));
    #pragma unroll
    for (int o = 16; o; o >>= 1) ss += __shfl_xor_sync(0xffffffffu, ss, o);
    __shared__ float wsum[8];
    __shared__ float sc;
    if ((t & 31) == 0) wsum[t >> 5] = ss;
    __syncthreads();
    if (t == 0) {
        float tot = 0.0f;
        #pragma unroll
        for (int i = 0; i < 8; i++) tot += wsum[i];
        sc = rsqrtf(tot / (float)D + 1e-5f);
    }
    __syncthreads();
    float scale = sc;
    float4 wv = *(const float4*)(w + t * 4);
    __half2 h01 = __floats2half2_rn(v.x * scale * wv.x, v.y * scale * wv.y);
    __half2 h23 = __floats2half2_rn(v.z * scale * wv.z, v.w * scale * wv.w);
    *(uint2*)(oh + (size_t)row * D + t * 4) = make_uint2(h2u(h01), h2u(h23));
}

// ---------------- weight transpose -> fp16, ALL layers ----------------
struct WcEnt { const float* src; __half* dh; int K; int N; int blkOff; size_t lsrc; };
struct WcArgs { WcEnt e[15]; };

__global__ void __launch_bounds__(256) k_wconv(WcArgs wa) {
    __shared__ float ts[32][33];
    int b = blockIdx.x;
    int lyr = blockIdx.y;
    int ei = 0;
    #pragma unroll
    for (int i = 14; i >= 1; i--) if (b >= wa.e[i].blkOff) { ei = i; break; }
    WcEnt E = wa.e[ei];
    const float* src = E.src + (size_t)lyr * E.lsrc;
    __half* dh = E.dh + (size_t)lyr * WL_STRIDE;
    int local = b - E.blkOff;
    int ntx = E.N >> 5;
    int tn = (local % ntx) << 5;
    int tk = (local / ntx) << 5;
    int t = threadIdx.x;
    {
        int row = t >> 3, c4 = (t & 7) << 2;
        float4 v = *(const float4*)(src + (size_t)(tk + row) * E.N + tn + c4);
        ts[row][c4 + 0] = v.x;
        ts[row][c4 + 1] = v.y;
        ts[row][c4 + 2] = v.z;
        ts[row][c4 + 3] = v.w;
    }
    __syncthreads();
    {
        int n = t >> 3, kq = (t & 7) << 2;
        __half2 h01 = __floats2half2_rn(ts[kq + 0][n], ts[kq + 1][n]);
        __half2 h23 = __floats2half2_rn(ts[kq + 2][n], ts[kq + 3][n]);
        *(uint2*)(dh + (size_t)(tn + n) * E.K + tk + kq) = make_uint2(h2u(h01), h2u(h23));
    }
}

// ---------------- plain f32 -> fp16 ----------------
__global__ void k_split(const float* __restrict__ src, __half* __restrict__ dh, int n) {
    int i = (blockIdx.x * 256 + threadIdx.x) * 8;
    if (i >= n) return;
    float4 a = *(const float4*)(src + i);
    float4 b = *(const float4*)(src + i + 4);
    uint4 o;
    o.x = h2u(__floats2half2_rn(a.x, a.y));
    o.y = h2u(__floats2half2_rn(a.z, a.w));
    o.z = h2u(__floats2half2_rn(b.x, b.y));
    o.w = h2u(__floats2half2_rn(b.z, b.w));
    *(uint4*)(dh + i) = o;
}

// ---------------- shared MMA helpers ----------------
__device__ __forceinline__ void mma16816(float* c, const unsigned* a, const unsigned* b) {
    asm volatile(
        "mma.sync.aligned.m16n8k16.row.col.f32.f16.f16.f32 "
        "{%0,%1,%2,%3}, {%4,%5,%6,%7}, {%8,%9}, {%0,%1,%2,%3};"
        : "+f"(c[0]), "+f"(c[1]), "+f"(c[2]), "+f"(c[3])
        : "r"(a[0]), "r"(a[1]), "r"(a[2]), "r"(a[3]), "r"(b[0]), "r"(b[1]));
}
__device__ __forceinline__ void ldsm4(unsigned* r, unsigned addr) {
    asm volatile("ldmatrix.sync.aligned.m8n8.x4.shared.b16 {%0,%1,%2,%3}, [%4];"
                 : "=r"(r[0]), "=r"(r[1]), "=r"(r[2]), "=r"(r[3]) : "r"(addr));
}
__device__ __forceinline__ void ldsm4t(unsigned* r, unsigned addr) {
    asm volatile("ldmatrix.sync.aligned.m8n8.x4.trans.shared.b16 {%0,%1,%2,%3}, [%4];"
                 : "=r"(r[0]), "=r"(r[1]), "=r"(r[2]), "=r"(r[3]) : "r"(addr));
}
__device__ __forceinline__ void cpasync16(unsigned saddr, const void* gptr) {
    asm volatile("cp.async.cg.shared.global [%0], [%1], 16;"
                 :: "r"(saddr), "l"(gptr) : "memory");
}
__device__ __forceinline__ void cp_commit() {
    asm volatile("cp.async.commit_group;" ::: "memory");
}
template<int NN> __device__ __forceinline__ void cp_wait() {
    asm volatile("cp.async.wait_group %0;" :: "n"(NN) : "memory");
}

// =======================================================================
// HMMA GEMM: C = A@B^T (+C). 128x128 tile, BK=64, 2-stage, 2 CTA/SM.
// outHalf: write fp16 to Ch instead of f32 C (accFlag must be 0).
// =======================================================================
struct GArgs {
    const __half* Ah[11];
    const __half* Bh[11];
    float* C[11];
    __half* Ch[11];
    int mRows[11];
};

constexpr int SMEM_HM = 65536;

__global__ void __launch_bounds__(256, 2) k_hmma(GArgs ga, int N, int K,
                                                 int accFlag, int outHalf) {
    extern __shared__ __align__(128) char smraw[];
    const int z = blockIdx.z;
    const int mbase = blockIdx.y << 7;
    if (mbase >= ga.mRows[z]) return;
    const int nbase = blockIdx.x << 7;

    const __half* Ah = ga.Ah[z];
    const __half* Bh = ga.Bh[z];

    const int t = threadIdx.x;
    const int l = t & 31;
    const int w = t >> 5;
    const int wr = w >> 2;
    const int wc = w & 3;
    const unsigned sb = (unsigned)__cvta_generic_to_shared(smraw);

    auto load_stage = [&](int c, int s) {
        unsigned stg = sb + (unsigned)s * 32768u;
        int k0 = c << 6;
        #pragma unroll
        for (int i = 0; i < 4; i++) {
            int id = t + i * 256;
            int row = id >> 3, kc = id & 7;
            unsigned soff = stg + (unsigned)row * 128u + (unsigned)((kc ^ (row & 7)) << 4);
            size_t ao = (size_t)(mbase + row) * K + k0 + kc * 8;
            size_t bo = (size_t)(nbase + row) * K + k0 + kc * 8;
            cpasync16(soff,          Ah + ao);
            cpasync16(soff + 16384u, Bh + bo);
        }
        cp_commit();
    };

    float acc[4][4][4];
    #pragma unroll
    for (int i = 0; i < 4; i++)
        #pragma unroll
        for (int j = 0; j < 4; j++)
            #pragma unroll
            for (int q = 0; q < 4; q++) acc[i][j][q] = 0.0f;

    const int nc = K >> 6;
    load_stage(0, 0);
    if (nc > 1) load_stage(1, 1);

    for (int c = 0; c < nc; c++) {
        if (c + 1 < nc) cp_wait<1>(); else cp_wait<0>();
        __syncthreads();
        unsigned stg = sb + (unsigned)(c & 1) * 32768u;
        #pragma unroll
        for (int ks = 0; ks < 4; ks++) {
            unsigned aH[4][4], bH[2][4];
            #pragma unroll
            for (int mt = 0; mt < 4; mt++) {
                int row = wr * 64 + mt * 16 + (l & 15);
                int chunk = ks * 2 + (l >> 4);
                unsigned off = stg + (unsigned)row * 128u + (unsigned)((chunk ^ (row & 7)) << 4);
                ldsm4(aH[mt], off);
            }
            #pragma unroll
            for (int p = 0; p < 2; p++) {
                int nrow = wc * 32 + p * 16 + ((l >> 1) & 8) + (l & 7);
                int chunk = ks * 2 + ((l >> 3) & 1);
                unsigned off = stg + 16384u + (unsigned)nrow * 128u +
                               (unsigned)((chunk ^ (nrow & 7)) << 4);
                ldsm4(bH[p], off);
            }
            #pragma unroll
            for (int mt = 0; mt < 4; mt++)
                #pragma unroll
                for (int j = 0; j < 4; j++)
                    mma16816(acc[mt][j], aH[mt], &bH[j >> 1][(j & 1) * 2]);
        }
        __syncthreads();
        if (c + 2 < nc) load_stage(c + 2, c & 1);
    }

    int r0 = wr * 64 + (l >> 2);
    int c0 = wc * 32 + (l & 3) * 2;
    if (outHalf) {
        __half* Ch = ga.Ch[z];
        #pragma unroll
        for (int mt = 0; mt < 4; mt++) {
            #pragma unroll
            for (int j = 0; j < 4; j++) {
                int row = mbase + r0 + mt * 16;
                int col = nbase + c0 + j * 8;
                *(unsigned*)(Ch + (size_t)row * N + col) =
                    h2u(__floats2half2_rn(acc[mt][j][0], acc[mt][j][1]));
                *(unsigned*)(Ch + (size_t)(row + 8) * N + col) =
                    h2u(__floats2half2_rn(acc[mt][j][2], acc[mt][j][3]));
            }
        }
    } else {
        float* C = ga.C[z];
        #pragma unroll
        for (int mt = 0; mt < 4; mt++) {
            #pragma unroll
            for (int j = 0; j < 4; j++) {
                int row = mbase + r0 + mt * 16;
                int col = nbase + c0 + j * 8;
                float2 v01 = { acc[mt][j][0], acc[mt][j][1] };
                float2 v23 = { acc[mt][j][2], acc[mt][j][3] };
                float* p0 = C + (size_t)row * N + col;
                float* p1 = C + (size_t)(row + 8) * N + col;
                if (accFlag) {
                    float2 o0 = *(const float2*)p0;
                    float2 o1 = *(const float2*)p1;
                    v01.x += o0.x; v01.y += o0.y;
                    v23.x += o1.x; v23.y += o1.y;
                }
                *(float2*)p0 = v01;
                *(float2*)p1 = v23;
            }
        }
    }
}

// =======================================================================
// Split-K HMMA GEMM: C += A@B^T partials via atomicAdd. 128x128 tile,
// BK=64, 2-stage, 2 CTA/SM. blockIdx.z selects the K-segment.
// Residual must already be present in C.
// =======================================================================
__global__ void __launch_bounds__(256, 2) k_hmma_sk(const __half* __restrict__ Ah,
                                                    const __half* __restrict__ Bh,
                                                    float* __restrict__ C,
                                                    int N, int K, int ksplit) {
    extern __shared__ __align__(128) char smraw[];
    const int mbase = blockIdx.y << 7;
    const int nbase = blockIdx.x << 7;
    const int kseg = K / ksplit;
    const int kofs = blockIdx.z * kseg;

    const int t = threadIdx.x;
    const int l = t & 31;
    const int w = t >> 5;
    const int wr = w >> 2;
    const int wc = w & 3;
    const unsigned sb = (unsigned)__cvta_generic_to_shared(smraw);

    auto load_stage = [&](int c, int s) {
        unsigned stg = sb + (unsigned)s * 32768u;
        int k0 = kofs + (c << 6);
        #pragma unroll
        for (int i = 0; i < 4; i++) {
            int id = t + i * 256;
            int row = id >> 3, kc = id & 7;
            unsigned soff = stg + (unsigned)row * 128u + (unsigned)((kc ^ (row & 7)) << 4);
            size_t ao = (size_t)(mbase + row) * K + k0 + kc * 8;
            size_t bo = (size_t)(nbase + row) * K + k0 + kc * 8;
            cpasync16(soff,          Ah + ao);
            cpasync16(soff + 16384u, Bh + bo);
        }
        cp_commit();
    };

    float acc[4][4][4];
    #pragma unroll
    for (int i = 0; i < 4; i++)
        #pragma unroll
        for (int j = 0; j < 4; j++)
            #pragma unroll
            for (int q = 0; q < 4; q++) acc[i][j][q] = 0.0f;

    const int nc = kseg >> 6;
    load_stage(0, 0);
    if (nc > 1) load_stage(1, 1);

    for (int c = 0; c < nc; c++) {
        if (c + 1 < nc) cp_wait<1>(); else cp_wait<0>();
        __syncthreads();
        unsigned stg = sb + (unsigned)(c & 1) * 32768u;
        #pragma unroll
        for (int ks = 0; ks < 4; ks++) {
            unsigned aH[4][4], bH[2][4];
            #pragma unroll
            for (int mt = 0; mt < 4; mt++) {
                int row = wr * 64 + mt * 16 + (l & 15);
                int chunk = ks * 2 + (l >> 4);
                unsigned off = stg + (unsigned)row * 128u + (unsigned)((chunk ^ (row & 7)) << 4);
                ldsm4(aH[mt], off);
            }
            #pragma unroll
            for (int p = 0; p < 2; p++) {
                int nrow = wc * 32 + p * 16 + ((l >> 1) & 8) + (l & 7);
                int chunk = ks * 2 + ((l >> 3) & 1);
                unsigned off = stg + 16384u + (unsigned)nrow * 128u +
                               (unsigned)((chunk ^ (nrow & 7)) << 4);
                ldsm4(bH[p], off);
            }
            #pragma unroll
            for (int mt = 0; mt < 4; mt++)
                #pragma unroll
                for (int j = 0; j < 4; j++)
                    mma16816(acc[mt][j], aH[mt], &bH[j >> 1][(j & 1) * 2]);
        }
        __syncthreads();
        if (c + 2 < nc) load_stage(c + 2, c & 1);
    }

    int r0 = wr * 64 + (l >> 2);
    int c0 = wc * 32 + (l & 3) * 2;
    #pragma unroll
    for (int mt = 0; mt < 4; mt++) {
        #pragma unroll
        for (int j = 0; j < 4; j++) {
            int row = mbase + r0 + mt * 16;
            int col = nbase + c0 + j * 8;
            float* p0 = C + (size_t)row * N + col;
            float* p1 = C + (size_t)(row + 8) * N + col;
            atomicAdd(p0,     acc[mt][j][0]);
            atomicAdd(p0 + 1, acc[mt][j][1]);
            atomicAdd(p1,     acc[mt][j][2]);
            atomicAdd(p1 + 1, acc[mt][j][3]);
        }
    }
}

// =======================================================================
// Fused MLP: gh = silu(A@Bg^T) * (A@Bu^T), fp16 out. 128x64 tile.
// =======================================================================
__global__ void __launch_bounds__(256, 2) k_mlp(const __half* __restrict__ A,
                                                const __half* __restrict__ Bg,
                                                const __half* __restrict__ Bu,
                                                __half* __restrict__ Cg,
                                                int N, int K) {
    extern __shared__ __align__(128) char smraw[];
    const int mbase = blockIdx.y << 7;
    const int nbase = blockIdx.x << 6;

    const int t = threadIdx.x;
    const int l = t & 31;
    const int w = t >> 5;
    const int wr = w >> 2;
    const int wc = w & 3;
    const unsigned sb = (unsigned)__cvta_generic_to_shared(smraw);

    auto load_stage = [&](int c, int s) {
        unsigned stg = sb + (unsigned)s * 32768u;
        int k0 = c << 6;
        #pragma unroll
        for (int i = 0; i < 4; i++) {
            int id = t + i * 256;
            int row = id >> 3, kc = id & 7;
            unsigned soff = stg + (unsigned)row * 128u + (unsigned)((kc ^ (row & 7)) << 4);
            cpasync16(soff, A + (size_t)(mbase + row) * K + k0 + kc * 8);
        }
        #pragma unroll
        for (int i = 0; i < 2; i++) {
            int id = t + i * 256;
            int row = id >> 3, kc = id & 7;
            unsigned soff = stg + 16384u + (unsigned)row * 128u +
                            (unsigned)((kc ^ (row & 7)) << 4);
            size_t bo = (size_t)(nbase + row) * K + k0 + kc * 8;
            cpasync16(soff,         Bg + bo);
            cpasync16(soff + 8192u, Bu + bo);
        }
        cp_commit();
    };

    float ag[4][2][4], au[4][2][4];
    #pragma unroll
    for (int i = 0; i < 4; i++)
        #pragma unroll
        for (int j = 0; j < 2; j++)
            #pragma unroll
            for (int q = 0; q < 4; q++) { ag[i][j][q] = 0.0f; au[i][j][q] = 0.0f; }

    const int nc = K >> 6;
    load_stage(0, 0);
    load_stage(1, 1);

    for (int c = 0; c < nc; c++) {
        if (c + 1 < nc) cp_wait<1>(); else cp_wait<0>();
        __syncthreads();
        unsigned stg = sb + (unsigned)(c & 1) * 32768u;
        #pragma unroll
        for (int ks = 0; ks < 4; ks++) {
            unsigned aH[4][4], bG[4], bU[4];
            #pragma unroll
            for (int mt = 0; mt < 4; mt++) {
                int row = wr * 64 + mt * 16 + (l & 15);
                int chunk = ks * 2 + (l >> 4);
                unsigned off = stg + (unsigned)row * 128u + (unsigned)((chunk ^ (row & 7)) << 4);
                ldsm4(aH[mt], off);
            }
            {
                int nrow = wc * 16 + ((l >> 1) & 8) + (l & 7);
                int chunk = ks * 2 + ((l >> 3) & 1);
                unsigned off = stg + 16384u + (unsigned)nrow * 128u +
                               (unsigned)((chunk ^ (nrow & 7)) << 4);
                ldsm4(bG, off);
                ldsm4(bU, off + 8192u);
            }
            #pragma unroll
            for (int mt = 0; mt < 4; mt++)
                #pragma unroll
                for (int j = 0; j < 2; j++) {
                    mma16816(ag[mt][j], aH[mt], &bG[j * 2]);
                    mma16816(au[mt][j], aH[mt], &bU[j * 2]);
                }
        }
        __syncthreads();
        if (c + 2 < nc) load_stage(c + 2, c & 1);
    }

    int r0 = wr * 64 + (l >> 2);
    int c0 = wc * 16 + (l & 3) * 2;
    #pragma unroll
    for (int mt = 0; mt < 4; mt++) {
        #pragma unroll
        for (int j = 0; j < 2; j++) {
            int row = mbase + r0 + mt * 16;
            int col = nbase + c0 + j * 8;
            float g0 = ag[mt][j][0], g1 = ag[mt][j][1];
            float g2 = ag[mt][j][2], g3 = ag[mt][j][3];
            float v0 = g0 / (1.0f + expf(-g0)) * au[mt][j][0];
            float v1 = g1 / (1.0f + expf(-g1)) * au[mt][j][1];
            float v2 = g2 / (1.0f + expf(-g2)) * au[mt][j][2];
            float v3 = g3 / (1.0f + expf(-g3)) * au[mt][j][3];
            *(unsigned*)(Cg + (size_t)row * N + col)       = h2u(__floats2half2_rn(v0, v1));
            *(unsigned*)(Cg + (size_t)(row + 8) * N + col) = h2u(__floats2half2_rn(v2, v3));
        }
    }
}

// ---------------- rope + head-major reshape, vectorized (4 halves/thread) ----------------
struct RsOne {
    const __half* src;
    __half*       dst;
    int rows;
    int dstStride;
    int dstOff;
    int posBase;
    float scl;
};
struct RsArgs { RsOne e[11]; };

__global__ void __launch_bounds__(256) k_reshape(RsArgs ra, const float* __restrict__ cosT,
                                                 const float* __restrict__ sinT) {
    RsOne a = ra.e[blockIdx.y];
    int row = blockIdx.x;
    if (row >= a.rows) return;
    int t = threadIdx.x;
    int n = t * 4;              // 4 consecutive elements, same head, same rope half
    int h = n >> 6;
    int d = n & 63;

    const __half* sp = a.src + (size_t)row * 1024 + n;
    uint2 vraw = *(const uint2*)sp;
    __half2 v01 = *(__half2*)&vraw.x;
    __half2 v23 = *(__half2*)&vraw.y;
    float f0 = __low2float(v01), f1 = __high2float(v01);
    float f2 = __low2float(v23), f3 = __high2float(v23);

    float o0, o1, o2, o3;
    if (a.posBase >= 0) {
        int pos = a.posBase + row;
        int pd = (d < 32) ? d + 32 : d - 32;
        float psign = (d < 32) ? -1.0f : 1.0f;
        uint2 praw = *(const uint2*)(a.src + (size_t)row * 1024 + h * 64 + pd);
        __half2 p01 = *(__half2*)&praw.x;
        __half2 p23 = *(__half2*)&praw.y;
        float4 cs = *(const float4*)(cosT + pos * 64 + d);
        float4 sn = *(const float4*)(sinT + pos * 64 + d);
        o0 = f0 * cs.x + psign * __low2float(p01)  * sn.x;
        o1 = f1 * cs.y + psign * __high2float(p01) * sn.y;
        o2 = f2 * cs.z + psign * __low2float(p23)  * sn.z;
        o3 = f3 * cs.w + psign * __high2float(p23) * sn.w;
    } else {
        o0 = f0; o1 = f1; o2 = f2; o3 = f3;
    }
    float s = a.scl;
    __half* dp = a.dst + ((size_t)h * a.dstStride + a.dstOff + row) * 64 + d;
    *(uint2*)dp = make_uint2(h2u(__floats2half2_rn(o0 * s, o1 * s)),
                             h2u(__floats2half2_rn(o2 * s, o3 * s)));
}

// ---------------- HMMA flash attention, z-batched, double-buffered K/V ----------------
struct AtArgs {
    const __half* Q[3];  int nq[3];
    const __half* K1[3]; const __half* V1[3]; int len1[3]; int hs1[3];
    const __half* K2[3]; const __half* V2[3]; int len2[3]; int hs2[3];
    int P[3]; __half* OutH[3];
};

__global__ void __launch_bounds__(128) k_attn(AtArgs aa) {
    const int z = blockIdx.z;
    const int qb = blockIdx.x * 64;
    if (qb >= aa.nq[z]) return;
    const int nq = aa.nq[z], len1 = aa.len1[z], hs1 = aa.hs1[z];
    const int len2 = aa.len2[z], hs2 = aa.hs2[z], P = aa.P[z];
    const __half* K1 = aa.K1[z]; const __half* V1 = aa.V1[z];
    const __half* K2 = aa.K2[z]; const __half* V2 = aa.V2[z];
    __half* OutH = aa.OutH[z];

    const int h = blockIdx.y;
    const int t = threadIdx.x;
    const int l = t & 31;
    const int w = t >> 5;

    __shared__ __align__(16) __half sm[16384];
    const unsigned sb = (unsigned)__cvta_generic_to_shared(sm);

    const __half* Qh = aa.Q[z] + (size_t)h * nq * 64;
    const int qrow = qb + w * 16 + (l >> 2);
    const int qcol = (l & 3) * 2;
    unsigned qfr[4][4];
    #pragma unroll
    for (int dt = 0; dt < 4; dt++) {
        qfr[dt][0] = *(const unsigned*)(Qh + (size_t)qrow * 64 + dt * 16 + qcol);
        qfr[dt][1] = *(const unsigned*)(Qh + (size_t)(qrow + 8) * 64 + dt * 16 + qcol);
        qfr[dt][2] = *(const unsigned*)(Qh + (size_t)qrow * 64 + dt * 16 + 8 + qcol);
        qfr[dt][3] = *(const unsigned*)(Qh + (size_t)(qrow + 8) * 64 + dt * 16 + 8 + qcol);
    }

    float oacc[8][4];
    #pragma unroll
    for (int i = 0; i < 8; i++)
        #pragma unroll
        for (int q = 0; q < 4; q++) oacc[i][q] = 0.0f;
    float m0 = -1e30f, m1 = -1e30f, ls0 = 0.0f, ls1 = 0.0f;

    const int total = len1 + len2;
    const int eff = min(total, P + qb + 64);
    const int ntk = (eff + 63) >> 6;
    const int wqmin = qb + w * 16;

    auto load_kv = [&](int kt, int s) {
        #pragma unroll
        for (int i = 0; i < 4; i++) {
            int id = t + i * 128;
            int row = id >> 3, kc = id & 7;
            int j = kt * 64 + row;
            const __half *kp, *vp;
            if (j < len1) {
                kp = K1 + (size_t)h * hs1 + (size_t)j * 64;
                vp = V1 + (size_t)h * hs1 + (size_t)j * 64;
            } else {
                kp = K2 + (size_t)h * hs2 + (size_t)(j - len1) * 64;
                vp = V2 + (size_t)h * hs2 + (size_t)(j - len1) * 64;
            }
            unsigned soff = sb + (unsigned)s * 16384u + (unsigned)row * 128u +
                            (unsigned)((kc ^ (row & 7)) << 4);
            cpasync16(soff,         kp + kc * 8);
            cpasync16(soff + 8192u, vp + kc * 8);
        }
        cp_commit();
    };

    load_kv(0, 0);

    for (int kt = 0; kt < ntk; kt++) {
        if (kt + 1 < ntk) { load_kv(kt + 1, (kt + 1) & 1); cp_wait<1>(); }
        else cp_wait<0>();
        __syncthreads();
        unsigned stg = sb + (unsigned)(kt & 1) * 16384u;

        float sacc[8][4];
        #pragma unroll
        for (int i = 0; i < 8; i++)
            #pragma unroll
            for (int q = 0; q < 4; q++) sacc[i][q] = 0.0f;
        #pragma unroll
        for (int p = 0; p < 4; p++) {
            int nrow = p * 16 + ((l >> 1) & 8) + (l & 7);
            #pragma unroll
            for (int dt = 0; dt < 4; dt++) {
                int chunk = dt * 2 + ((l >> 3) & 1);
                unsigned off = stg + (unsigned)nrow * 128u + (unsigned)((chunk ^ (nrow & 7)) << 4);
                unsigned kfr[4];
                ldsm4(kfr, off);
                mma16816(sacc[2 * p],     qfr[dt], kfr);
                mma16816(sacc[2 * p + 1], qfr[dt], kfr + 2);
            }
        }

        int kg0 = kt * 64;
        if (!(kg0 + 63 < P || kg0 + 63 - P <= wqmin)) {
            #pragma unroll
            for (int nt = 0; nt < 8; nt++) {
                int col = kg0 + nt * 8 + qcol;
                if (!(col < P || col - P <= qrow))         sacc[nt][0] = -1e30f;
                if (!(col + 1 < P || col + 1 - P <= qrow)) sacc[nt][1] = -1e30f;
                if (!(col < P || col - P <= qrow + 8))         sacc[nt][2] = -1e30f;
                if (!(col + 1 < P || col + 1 - P <= qrow + 8)) sacc[nt][3] = -1e30f;
            }
        }

        float tm0 = -1e30f, tm1 = -1e30f;
        #pragma unroll
        for (int nt = 0; nt < 8; nt++) {
            tm0 = fmaxf(tm0, fmaxf(sacc[nt][0], sacc[nt][1]));
            tm1 = fmaxf(tm1, fmaxf(sacc[nt][2], sacc[nt][3]));
        }
        tm0 = fmaxf(tm0, __shfl_xor_sync(0xffffffffu, tm0, 1));
        tm0 = fmaxf(tm0, __shfl_xor_sync(0xffffffffu, tm0, 2));
        tm1 = fmaxf(tm1, __shfl_xor_sync(0xffffffffu, tm1, 1));
        tm1 = fmaxf(tm1, __shfl_xor_sync(0xffffffffu, tm1, 2));
        float nm0 = fmaxf(m0, tm0), nm1 = fmaxf(m1, tm1);
        float cr0 = __expf(m0 - nm0), cr1 = __expf(m1 - nm1);
        ls0 *= cr0; ls1 *= cr1;
        #pragma unroll
        for (int nt = 0; nt < 8; nt++) {
            oacc[nt][0] *= cr0; oacc[nt][1] *= cr0;
            oacc[nt][2] *= cr1; oacc[nt][3] *= cr1;
        }
        m0 = nm0; m1 = nm1;
        #pragma unroll
        for (int nt = 0; nt < 8; nt++) {
            sacc[nt][0] = __expf(sacc[nt][0] - nm0);
            sacc[nt][1] = __expf(sacc[nt][1] - nm0);
            sacc[nt][2] = __expf(sacc[nt][2] - nm1);
            sacc[nt][3] = __expf(sacc[nt][3] - nm1);
            ls0 += sacc[nt][0] + sacc[nt][1];
            ls1 += sacc[nt][2] + sacc[nt][3];
        }

        #pragma unroll
        for (int kt2 = 0; kt2 < 4; kt2++) {
            unsigned pfr[4];
            pfr[0] = h2u(__floats2half2_rn(sacc[2 * kt2][0],     sacc[2 * kt2][1]));
            pfr[1] = h2u(__floats2half2_rn(sacc[2 * kt2][2],     sacc[2 * kt2][3]));
            pfr[2] = h2u(__floats2half2_rn(sacc[2 * kt2 + 1][0], sacc[2 * kt2 + 1][1]));
            pfr[3] = h2u(__floats2half2_rn(sacc[2 * kt2 + 1][2], sacc[2 * kt2 + 1][3]));
            int vrow = kt2 * 16 + (l & 15);
            #pragma unroll
            for (int dv = 0; dv < 4; dv++) {
                int chunk = dv * 2 + (l >> 4);
                unsigned off = stg + 8192u + (unsigned)vrow * 128u +
                               (unsigned)((chunk ^ (vrow & 7)) << 4);
                unsigned vf4[4];
                ldsm4t(vf4, off);
                mma16816(oacc[2 * dv],     pfr, vf4);
                mma16816(oacc[2 * dv + 1], pfr, vf4 + 2);
            }
        }
        __syncthreads();
    }

    ls0 += __shfl_xor_sync(0xffffffffu, ls0, 1);
    ls0 += __shfl_xor_sync(0xffffffffu, ls0, 2);
    ls1 += __shfl_xor_sync(0xffffffffu, ls1, 1);
    ls1 += __shfl_xor_sync(0xffffffffu, ls1, 2);
    float inv0 = 1.0f / ls0, inv1 = 1.0f / ls1;
    __half* op0 = OutH + (size_t)qrow * 1024 + h * 64 + qcol;
    __half* op1 = OutH + (size_t)(qrow + 8) * 1024 + h * 64 + qcol;
    #pragma unroll
    for (int nt = 0; nt < 8; nt++) {
        *(unsigned*)(op0 + nt * 8) = h2u(__floats2half2_rn(oacc[nt][0] * inv0,
                                                           oacc[nt][1] * inv0));
        *(unsigned*)(op1 + nt * 8) = h2u(__floats2half2_rn(oacc[nt][2] * inv1,
                                                           oacc[nt][3] * inv1));
    }
}

// ---------------- host driver ----------------
extern "C" void kernel_launch(void* const* d_in, const int* in_sizes, int n_in,
                              void* d_out, int out_size) {
    (void)in_sizes; (void)n_in; (void)out_size;

    const int*   ids    = (const int*)  d_in[0];
    const float* memory = (const float*)d_in[1];
    const float* beacon = (const float*)d_in[2];
    const float* forget = (const float*)d_in[3];
    const float* embed  = (const float*)d_in[4];
    const float* ln1    = (const float*)d_in[5];
    const float* ln2    = (const float*)d_in[6];
    const float* Wsrc[12] = {
        (const float*)d_in[7],  (const float*)d_in[8],  (const float*)d_in[9],
        (const float*)d_in[10], (const float*)d_in[11], (const float*)d_in[12],
        (const float*)d_in[13], (const float*)d_in[14], (const float*)d_in[15],
        (const float*)d_in[16], (const float*)d_in[17], (const float*)d_in[18]
    };
    const float* Wg = (const float*)d_in[19];
    const float* Wu = (const float*)d_in[20];
    const float* Wd = (const float*)d_in[21];
    float* out = (float*)d_out;

    float* pool = nullptr;
    cudaGetSymbolAddress((void**)&pool, g_pool);
    __half* hp = nullptr;
    cudaGetSymbolAddress((void**)&hp, g_poolhf);

    float* cat  = pool + OFF_CAT;
    float* cosT = pool + OFF_COS;
    float* sinT = pool + OFF_SIN;
    __half* tqkv_h = (__half*)(pool + OFF_TQKV);
    __half* tsm_h  = tqkv_h + 3u * 1048576u;

    __half* xh = hp + B_XH;
    __half* ah = hp + B_AH;
    __half* yh = hp + B_YH;
    __half* gh = hp + B_GH;
    __half* mehAll = hp + B_MEH;
    __half* qh   = hp + HB_Q;
    __half* qbh  = hp + HB_QB;
    __half* qfh  = hp + HB_QF;
    __half* kbuf = hp + HB_K;
    __half* vbuf = hp + HB_V;
    __half* kf   = hp + HB_KF;
    __half* vf   = hp + HB_VF;

    cudaFuncSetAttribute(k_hmma,    cudaFuncAttributeMaxDynamicSharedMemorySize, SMEM_HM);
    cudaFuncSetAttribute(k_hmma_sk, cudaFuncAttributeMaxDynamicSharedMemorySize, SMEM_HM);
    cudaFuncSetAttribute(k_mlp,     cudaFuncAttributeMaxDynamicSharedMemorySize, SMEM_HM);

    const size_t WDD = (size_t)D * D;
    const size_t WDF = (size_t)D * F;
    const size_t WFD = (size_t)F * D;
    const size_t MDsz = (size_t)Mm * D;

    // ---- pre-loop ----
    k_tables<<<(1280 * 64 + 255) / 256, 256>>>(cosT, sinT);
    k_fillcat<<<(TOT * D + 255) / 256, 256>>>(cat, ids, embed, beacon, forget);
    {
        WcArgs wa;
        int off = 0;
        for (int i = 0; i < 12; i++) {
            wa.e[i] = { Wsrc[i], hp + BW_ALL + (size_t)i * 1048576, D, D, off, WDD };
            off += (D / 32) * (D / 32);
        }
        wa.e[12] = { Wg, hp + BW_ALL + 12582912, D, F, off, WDF }; off += (D/32)*(F/32);
        wa.e[13] = { Wu, hp + BW_ALL + 14680064, D, F, off, WDF }; off += (D/32)*(F/32);
        wa.e[14] = { Wd, hp + BW_ALL + 16777216, F, D, off, WFD }; off += (F/32)*(D/32);
        k_wconv<<<dim3(off, L), 256>>>(wa);
    }
    k_split<<<(L * Mm * D / 8 + 255) / 256, 256>>>(memory, mehAll, L * Mm * D);

    for (int l = 0; l < L; l++) {
        const float* mem_l = memory + (size_t)l * MDsz;
        __half* base_w = hp + BW_ALL + (size_t)l * WL_STRIDE;
        __half* wtH[15];
        for (int i = 0; i < 12; i++) wtH[i] = base_w + (size_t)i * 1048576;
        wtH[12] = base_w + 12582912;
        wtH[13] = base_w + 14680064;
        wtH[14] = base_w + 16777216;
        __half* meh = mehAll + (size_t)l * MDsz;

        k_rms<<<TOT + Mm, 256>>>(cat, ln1 + (size_t)l * D, xh,
                                 mem_l, out + (size_t)l * MDsz);

        // QKV + eight 128-row projections -> fp16 outputs
        {
            GArgs ga = {};
            for (int z = 0; z < 3; z++) {
                ga.Ah[z] = xh;
                ga.Bh[z] = wtH[z];
                ga.Ch[z] = tqkv_h + (size_t)z * 1048576;
                ga.mRows[z] = S;
            }
            const __half* bxh = xh + (size_t)S * D;
            const __half* fxh = xh + (size_t)(S + Mm) * D;
            const __half* sAh[8] = { meh, meh, bxh, bxh, bxh, fxh, fxh, fxh };
            int wmap[8] = {4, 5, 6, 7, 8, 9, 10, 11};
            for (int z = 0; z < 8; z++) {
                ga.Ah[3 + z] = sAh[z];
                ga.Bh[3 + z] = wtH[wmap[z]];
                ga.Ch[3 + z] = tsm_h + (size_t)z * 131072;
                ga.mRows[3 + z] = Mm;
            }
            k_hmma<<<dim3(8, 8, 11), 256, SMEM_HM>>>(ga, D, D, 0, 1);
        }
        // rope + reshape (vectorized; Q scaled by 0.125)
        {
            RsArgs ra;
            ra.e[0]  = { tqkv_h,            qh,   S,  1024, 0,    Mm,   0.125f };
            ra.e[1]  = { tqkv_h + 1048576,  kbuf, S,  1280, 128,  Mm,   1.0f };
            ra.e[2]  = { tqkv_h + 2097152,  vbuf, S,  1280, 128,  -1,   1.0f };
            ra.e[3]  = { tsm_h,             kbuf, Mm, 1280, 0,    0,    1.0f };
            ra.e[4]  = { tsm_h + 131072,    vbuf, Mm, 1280, 0,    -1,   1.0f };
            ra.e[5]  = { tsm_h + 262144,    qbh,  Mm, 128,  0,    KHID, 0.125f };
            ra.e[6]  = { tsm_h + 393216,    kbuf, Mm, 1280, KHID, KHID, 1.0f };
            ra.e[7]  = { tsm_h + 524288,    vbuf, Mm, 1280, KHID, -1,   1.0f };
            ra.e[8]  = { tsm_h + 655360,    qfh,  Mm, 128,  0,    KHID, 0.125f };
            ra.e[9]  = { tsm_h + 786432,    kf,   Mm, 128,  0,    KHID, 1.0f };
            ra.e[10] = { tsm_h + 917504,    vf,   Mm, 128,  0,    -1,   1.0f };
            k_reshape<<<dim3(1024, 11), 256>>>(ra, cosT, sinT);
        }
        // attention
        {
            AtArgs aa;
            aa.Q[0] = qh;    aa.nq[0] = S;
            aa.K1[0] = kbuf; aa.V1[0] = vbuf; aa.len1[0] = KHID; aa.hs1[0] = 1280 * 64;
            aa.K2[0] = kf;   aa.V2[0] = vf;   aa.len2[0] = 0;    aa.hs2[0] = 128 * 64;
            aa.P[0] = Mm;    aa.OutH[0] = ah;
            aa.Q[1] = qbh;   aa.nq[1] = Mm;
            aa.K1[1] = kbuf; aa.V1[1] = vbuf; aa.len1[1] = TOT;  aa.hs1[1] = 1280 * 64;
            aa.K2[1] = kf;   aa.V2[1] = vf;   aa.len2[1] = 0;    aa.hs2[1] = 128 * 64;
            aa.P[1] = KHID;  aa.OutH[1] = ah + (size_t)S * D;
            aa.Q[2] = qfh;   aa.nq[2] = Mm;
            aa.K1[2] = kbuf; aa.V1[2] = vbuf; aa.len1[2] = KHID; aa.hs1[2] = 1280 * 64;
            aa.K2[2] = kf;   aa.V2[2] = vf;   aa.len2[2] = Mm;   aa.hs2[2] = 128 * 64;
            aa.P[2] = KHID;  aa.OutH[2] = ah + (size_t)KHID * D;
            k_attn<<<dim3(S / 64, H, 3), 128>>>(aa);
        }
        // Wo (+residual already in cat) — split-K=4: 320 CTAs, nc=4 per CTA
        k_hmma_sk<<<dim3(8, 10, 4), 256, SMEM_HM>>>(ah, wtH[3], cat, D, D, 4);
        k_rms<<<TOT, 256>>>(cat, ln2 + (size_t)l * D, yh, nullptr, nullptr);
        // fused MLP
        k_mlp<<<dim3(F / 64, TOT / 128), 256, SMEM_HM>>>(yh, wtH[12], wtH[13], gh, F, D);
        // down (+residual already in cat) — split-K=4: nc=8 per CTA
        k_hmma_sk<<<dim3(8, 10, 4), 256, SMEM_HM>>>(gh, wtH[14], cat, D, F, 4);
    }
}

// round 17
// speedup vs baseline: 1.2219x; 1.0443x over previous
#include <cuda_runtime.h>
#include <cuda_fp16.h>
#include <math.h>

// Problem constants
constexpr int S  = 1024;
constexpr int Mm = 128;
constexpr int D  = 1024;
constexpr int H  = 16;
constexpr int HD = 64;
constexpr int F  = 2048;
constexpr int L  = 8;
constexpr int TOT = S + 2 * Mm;     // 1280
constexpr int KHID = Mm + S;        // 1152

// ---------------- f32 scratch pool ----------------
constexpr size_t OFF_CAT  = 0;                          // 1280*1024
constexpr size_t OFF_TQKV = 9437184;                    // reused as fp16 area
constexpr size_t OFF_COS  = 18874368;
constexpr size_t OFF_SIN  = 18956288;
constexpr size_t POOL_SZ  = 19038208;
__device__ __align__(16) float g_pool[POOL_SZ];

// ---------------- fp16 scratch pool ----------------
constexpr size_t WL_STRIDE = 18874368;   // per-layer: 12*1048576 + 3*2097152
constexpr size_t BW_ALL   = 0;           // 8 layers of converted weights
constexpr size_t B_XH     = 150994944;   // 1280*1024
constexpr size_t B_AH     = 152305664;
constexpr size_t B_YH     = 153616384;
constexpr size_t B_GH     = 154927104;   // 1280*2048
constexpr size_t B_MEH    = 157548544;   // 8 * 128*1024
constexpr size_t HB_Q     = 158597120;   // 16*1024*64
constexpr size_t HB_QB    = 159645696;   // 16*128*64
constexpr size_t HB_QF    = 159776768;
constexpr size_t HB_K     = 159907840;   // 16*1280*64
constexpr size_t HB_V     = 161218560;
constexpr size_t HB_KF    = 162529280;   // 16*128*64
constexpr size_t HB_VF    = 162660352;
constexpr size_t BPOOL_SZ = 162791424;
__device__ __align__(16) __half g_poolhf[BPOOL_SZ];

__device__ __forceinline__ unsigned h2u(__half2 h) { return *(unsigned*)&h; }

// ---------------- rope tables ----------------
__global__ void k_tables(float* cosT, float* sinT) {
    int idx = blockIdx.x * blockDim.x + threadIdx.x;
    if (idx >= 1280 * 64) return;
    int p = idx >> 6;
    int d = idx & 63;
    int i = d & 31;
    double inv = pow(10000.0, -((double)i) / 32.0);
    double ang = (double)p * inv;
    cosT[idx] = (float)cos(ang);
    sinT[idx] = (float)sin(ang);
}

// ---------------- initial residual ----------------
__global__ void k_fillcat(float* cat, const int* __restrict__ ids,
                          const float* __restrict__ embed,
                          const float* __restrict__ beacon,
                          const float* __restrict__ forget) {
    int idx = blockIdx.x * blockDim.x + threadIdx.x;
    if (idx >= TOT * D) return;
    int row = idx >> 10;
    int d = idx & 1023;
    float v;
    if (row < S)            v = embed[(size_t)ids[row] * D + d];
    else if (row < S + Mm)  v = beacon[(size_t)(row - S) * D + d];
    else                    v = forget[(size_t)(row - S - Mm) * D + d];
    cat[idx] = v;
}

// ---------------- rmsnorm -> fp16, fused gated-output ----------------
__global__ void k_rms(const float* __restrict__ in, const float* __restrict__ w,
                      __half* __restrict__ oh,
                      const float* __restrict__ mem, float* __restrict__ outg) {
    int row = blockIdx.x;
    int t = threadIdx.x;
    if (row >= TOT) {
        int idx = (row - TOT) * 1024 + t * 4;
        float4 bcn = *(const float4*)(in + (size_t)S * D + idx);
        float4 fgt = *(const float4*)(in + (size_t)(S + Mm) * D + idx);
        float4 mv  = *(const float4*)(mem + idx);
        float4 o;
        float g;
        g = 1.0f / (1.0f + expf(-fgt.x)); o.x = mv.x * g + bcn.x * (1.0f - g);
        g = 1.0f / (1.0f + expf(-fgt.y)); o.y = mv.y * g + bcn.y * (1.0f - g);
        g = 1.0f / (1.0f + expf(-fgt.z)); o.z = mv.z * g + bcn.z * (1.0f - g);
        g = 1.0f / (1.0f + expf(-fgt.w)); o.w = mv.w * g + bcn.w * (1.0f - g);
        *(float4*)(outg + idx) = o;
        return;
    }
    const float* r = in + (size_t)row * D;
    float4 v = *(const float4*)(r + t * 4);
    float ss = fmaf(v.x, v.x, fmaf(v.y, v.y, fmaf(v.z, v.z, v.w * v.w)));
    #pragma unroll
    for (int o = 16; o; o >>= 1) ss += __shfl_xor_sync(0xffffffffu, ss, o);
    __shared__ float wsum[8];
    __shared__ float sc;
    if ((t & 31) == 0) wsum[t >> 5] = ss;
    __syncthreads();
    if (t == 0) {
        float tot = 0.0f;
        #pragma unroll
        for (int i = 0; i < 8; i++) tot += wsum[i];
        sc = rsqrtf(tot / (float)D + 1e-5f);
    }
    __syncthreads();
    float scale = sc;
    float4 wv = *(const float4*)(w + t * 4);
    __half2 h01 = __floats2half2_rn(v.x * scale * wv.x, v.y * scale * wv.y);
    __half2 h23 = __floats2half2_rn(v.z * scale * wv.z, v.w * scale * wv.w);
    *(uint2*)(oh + (size_t)row * D + t * 4) = make_uint2(h2u(h01), h2u(h23));
}

// ---------------- weight transpose -> fp16, ALL layers, 64x64 tiles ----------------
struct WcEnt { const float* src; __half* dh; int K; int N; int blkOff; size_t lsrc; };
struct WcArgs { WcEnt e[15]; };

__global__ void __launch_bounds__(256) k_wconv(WcArgs wa) {
    __shared__ float ts[64][65];
    int b = blockIdx.x;
    int lyr = blockIdx.y;
    int ei = 0;
    #pragma unroll
    for (int i = 14; i >= 1; i--) if (b >= wa.e[i].blkOff) { ei = i; break; }
    WcEnt E = wa.e[ei];
    const float* src = E.src + (size_t)lyr * E.lsrc;
    __half* dh = E.dh + (size_t)lyr * WL_STRIDE;
    int local = b - E.blkOff;
    int ntx = E.N >> 6;
    int tn = (local % ntx) << 6;
    int tk = (local / ntx) << 6;
    int t = threadIdx.x;
    // load 64x64 f32 tile (rows = K dim, cols = N dim); 16 floats/thread
    #pragma unroll
    for (int p = 0; p < 4; p++) {
        int row = (t >> 4) + p * 16;
        int c4 = (t & 15) << 2;
        float4 v = *(const float4*)(src + (size_t)(tk + row) * E.N + tn + c4);
        ts[row][c4 + 0] = v.x;
        ts[row][c4 + 1] = v.y;
        ts[row][c4 + 2] = v.z;
        ts[row][c4 + 3] = v.w;
    }
    __syncthreads();
    // store transposed as fp16: out rows = N dim, 128B per row (fully coalesced)
    #pragma unroll
    for (int p = 0; p < 4; p++) {
        int n = (t >> 4) + p * 16;
        int kq = (t & 15) << 2;
        __half2 h01 = __floats2half2_rn(ts[kq + 0][n], ts[kq + 1][n]);
        __half2 h23 = __floats2half2_rn(ts[kq + 2][n], ts[kq + 3][n]);
        *(uint2*)(dh + (size_t)(tn + n) * E.K + tk + kq) = make_uint2(h2u(h01), h2u(h23));
    }
}

// ---------------- plain f32 -> fp16 ----------------
__global__ void k_split(const float* __restrict__ src, __half* __restrict__ dh, int n) {
    int i = (blockIdx.x * 256 + threadIdx.x) * 8;
    if (i >= n) return;
    float4 a = *(const float4*)(src + i);
    float4 b = *(const float4*)(src + i + 4);
    uint4 o;
    o.x = h2u(__floats2half2_rn(a.x, a.y));
    o.y = h2u(__floats2half2_rn(a.z, a.w));
    o.z = h2u(__floats2half2_rn(b.x, b.y));
    o.w = h2u(__floats2half2_rn(b.z, b.w));
    *(uint4*)(dh + i) = o;
}

// ---------------- shared MMA helpers ----------------
__device__ __forceinline__ void mma16816(float* c, const unsigned* a, const unsigned* b) {
    asm volatile(
        "mma.sync.aligned.m16n8k16.row.col.f32.f16.f16.f32 "
        "{%0,%1,%2,%3}, {%4,%5,%6,%7}, {%8,%9}, {%0,%1,%2,%3};"
        : "+f"(c[0]), "+f"(c[1]), "+f"(c[2]), "+f"(c[3])
        : "r"(a[0]), "r"(a[1]), "r"(a[2]), "r"(a[3]), "r"(b[0]), "r"(b[1]));
}
__device__ __forceinline__ void ldsm4(unsigned* r, unsigned addr) {
    asm volatile("ldmatrix.sync.aligned.m8n8.x4.shared.b16 {%0,%1,%2,%3}, [%4];"
                 : "=r"(r[0]), "=r"(r[1]), "=r"(r[2]), "=r"(r[3]) : "r"(addr));
}
__device__ __forceinline__ void ldsm4t(unsigned* r, unsigned addr) {
    asm volatile("ldmatrix.sync.aligned.m8n8.x4.trans.shared.b16 {%0,%1,%2,%3}, [%4];"
                 : "=r"(r[0]), "=r"(r[1]), "=r"(r[2]), "=r"(r[3]) : "r"(addr));
}
__device__ __forceinline__ void cpasync16(unsigned saddr, const void* gptr) {
    asm volatile("cp.async.cg.shared.global [%0], [%1], 16;"
                 :: "r"(saddr), "l"(gptr) : "memory");
}
__device__ __forceinline__ void cp_commit() {
    asm volatile("cp.async.commit_group;" ::: "memory");
}
template<int NN> __device__ __forceinline__ void cp_wait() {
    asm volatile("cp.async.wait_group %0;" :: "n"(NN) : "memory");
}

// =======================================================================
// HMMA GEMM: C = A@B^T (+C). 128x128 tile, BK=64, 2-stage, 2 CTA/SM.
// outHalf: write fp16 to Ch instead of f32 C (accFlag must be 0).
// =======================================================================
struct GArgs {
    const __half* Ah[11];
    const __half* Bh[11];
    float* C[11];
    __half* Ch[11];
    int mRows[11];
};

constexpr int SMEM_HM = 65536;

__global__ void __launch_bounds__(256, 2) k_hmma(GArgs ga, int N, int K,
                                                 int accFlag, int outHalf) {
    extern __shared__ __align__(128) char smraw[];
    const int z = blockIdx.z;
    const int mbase = blockIdx.y << 7;
    if (mbase >= ga.mRows[z]) return;
    const int nbase = blockIdx.x << 7;

    const __half* Ah = ga.Ah[z];
    const __half* Bh = ga.Bh[z];

    const int t = threadIdx.x;
    const int l = t & 31;
    const int w = t >> 5;
    const int wr = w >> 2;
    const int wc = w & 3;
    const unsigned sb = (unsigned)__cvta_generic_to_shared(smraw);

    auto load_stage = [&](int c, int s) {
        unsigned stg = sb + (unsigned)s * 32768u;
        int k0 = c << 6;
        #pragma unroll
        for (int i = 0; i < 4; i++) {
            int id = t + i * 256;
            int row = id >> 3, kc = id & 7;
            unsigned soff = stg + (unsigned)row * 128u + (unsigned)((kc ^ (row & 7)) << 4);
            size_t ao = (size_t)(mbase + row) * K + k0 + kc * 8;
            size_t bo = (size_t)(nbase + row) * K + k0 + kc * 8;
            cpasync16(soff,          Ah + ao);
            cpasync16(soff + 16384u, Bh + bo);
        }
        cp_commit();
    };

    float acc[4][4][4];
    #pragma unroll
    for (int i = 0; i < 4; i++)
        #pragma unroll
        for (int j = 0; j < 4; j++)
            #pragma unroll
            for (int q = 0; q < 4; q++) acc[i][j][q] = 0.0f;

    const int nc = K >> 6;
    load_stage(0, 0);
    if (nc > 1) load_stage(1, 1);

    for (int c = 0; c < nc; c++) {
        if (c + 1 < nc) cp_wait<1>(); else cp_wait<0>();
        __syncthreads();
        unsigned stg = sb + (unsigned)(c & 1) * 32768u;
        #pragma unroll
        for (int ks = 0; ks < 4; ks++) {
            unsigned aH[4][4], bH[2][4];
            #pragma unroll
            for (int mt = 0; mt < 4; mt++) {
                int row = wr * 64 + mt * 16 + (l & 15);
                int chunk = ks * 2 + (l >> 4);
                unsigned off = stg + (unsigned)row * 128u + (unsigned)((chunk ^ (row & 7)) << 4);
                ldsm4(aH[mt], off);
            }
            #pragma unroll
            for (int p = 0; p < 2; p++) {
                int nrow = wc * 32 + p * 16 + ((l >> 1) & 8) + (l & 7);
                int chunk = ks * 2 + ((l >> 3) & 1);
                unsigned off = stg + 16384u + (unsigned)nrow * 128u +
                               (unsigned)((chunk ^ (nrow & 7)) << 4);
                ldsm4(bH[p], off);
            }
            #pragma unroll
            for (int mt = 0; mt < 4; mt++)
                #pragma unroll
                for (int j = 0; j < 4; j++)
                    mma16816(acc[mt][j], aH[mt], &bH[j >> 1][(j & 1) * 2]);
        }
        __syncthreads();
        if (c + 2 < nc) load_stage(c + 2, c & 1);
    }

    int r0 = wr * 64 + (l >> 2);
    int c0 = wc * 32 + (l & 3) * 2;
    if (outHalf) {
        __half* Ch = ga.Ch[z];
        #pragma unroll
        for (int mt = 0; mt < 4; mt++) {
            #pragma unroll
            for (int j = 0; j < 4; j++) {
                int row = mbase + r0 + mt * 16;
                int col = nbase + c0 + j * 8;
                *(unsigned*)(Ch + (size_t)row * N + col) =
                    h2u(__floats2half2_rn(acc[mt][j][0], acc[mt][j][1]));
                *(unsigned*)(Ch + (size_t)(row + 8) * N + col) =
                    h2u(__floats2half2_rn(acc[mt][j][2], acc[mt][j][3]));
            }
        }
    } else {
        float* C = ga.C[z];
        #pragma unroll
        for (int mt = 0; mt < 4; mt++) {
            #pragma unroll
            for (int j = 0; j < 4; j++) {
                int row = mbase + r0 + mt * 16;
                int col = nbase + c0 + j * 8;
                float2 v01 = { acc[mt][j][0], acc[mt][j][1] };
                float2 v23 = { acc[mt][j][2], acc[mt][j][3] };
                float* p0 = C + (size_t)row * N + col;
                float* p1 = C + (size_t)(row + 8) * N + col;
                if (accFlag) {
                    float2 o0 = *(const float2*)p0;
                    float2 o1 = *(const float2*)p1;
                    v01.x += o0.x; v01.y += o0.y;
                    v23.x += o1.x; v23.y += o1.y;
                }
                *(float2*)p0 = v01;
                *(float2*)p1 = v23;
            }
        }
    }
}

// =======================================================================
// Split-K HMMA GEMM: C += A@B^T partials via atomicAdd. 128x128 tile,
// BK=64, 2-stage, 2 CTA/SM. blockIdx.z selects the K-segment.
// Residual must already be present in C.
// =======================================================================
__global__ void __launch_bounds__(256, 2) k_hmma_sk(const __half* __restrict__ Ah,
                                                    const __half* __restrict__ Bh,
                                                    float* __restrict__ C,
                                                    int N, int K, int ksplit) {
    extern __shared__ __align__(128) char smraw[];
    const int mbase = blockIdx.y << 7;
    const int nbase = blockIdx.x << 7;
    const int kseg = K / ksplit;
    const int kofs = blockIdx.z * kseg;

    const int t = threadIdx.x;
    const int l = t & 31;
    const int w = t >> 5;
    const int wr = w >> 2;
    const int wc = w & 3;
    const unsigned sb = (unsigned)__cvta_generic_to_shared(smraw);

    auto load_stage = [&](int c, int s) {
        unsigned stg = sb + (unsigned)s * 32768u;
        int k0 = kofs + (c << 6);
        #pragma unroll
        for (int i = 0; i < 4; i++) {
            int id = t + i * 256;
            int row = id >> 3, kc = id & 7;
            unsigned soff = stg + (unsigned)row * 128u + (unsigned)((kc ^ (row & 7)) << 4);
            size_t ao = (size_t)(mbase + row) * K + k0 + kc * 8;
            size_t bo = (size_t)(nbase + row) * K + k0 + kc * 8;
            cpasync16(soff,          Ah + ao);
            cpasync16(soff + 16384u, Bh + bo);
        }
        cp_commit();
    };

    float acc[4][4][4];
    #pragma unroll
    for (int i = 0; i < 4; i++)
        #pragma unroll
        for (int j = 0; j < 4; j++)
            #pragma unroll
            for (int q = 0; q < 4; q++) acc[i][j][q] = 0.0f;

    const int nc = kseg >> 6;
    load_stage(0, 0);
    if (nc > 1) load_stage(1, 1);

    for (int c = 0; c < nc; c++) {
        if (c + 1 < nc) cp_wait<1>(); else cp_wait<0>();
        __syncthreads();
        unsigned stg = sb + (unsigned)(c & 1) * 32768u;
        #pragma unroll
        for (int ks = 0; ks < 4; ks++) {
            unsigned aH[4][4], bH[2][4];
            #pragma unroll
            for (int mt = 0; mt < 4; mt++) {
                int row = wr * 64 + mt * 16 + (l & 15);
                int chunk = ks * 2 + (l >> 4);
                unsigned off = stg + (unsigned)row * 128u + (unsigned)((chunk ^ (row & 7)) << 4);
                ldsm4(aH[mt], off);
            }
            #pragma unroll
            for (int p = 0; p < 2; p++) {
                int nrow = wc * 32 + p * 16 + ((l >> 1) & 8) + (l & 7);
                int chunk = ks * 2 + ((l >> 3) & 1);
                unsigned off = stg + 16384u + (unsigned)nrow * 128u +
                               (unsigned)((chunk ^ (nrow & 7)) << 4);
                ldsm4(bH[p], off);
            }
            #pragma unroll
            for (int mt = 0; mt < 4; mt++)
                #pragma unroll
                for (int j = 0; j < 4; j++)
                    mma16816(acc[mt][j], aH[mt], &bH[j >> 1][(j & 1) * 2]);
        }
        __syncthreads();
        if (c + 2 < nc) load_stage(c + 2, c & 1);
    }

    int r0 = wr * 64 + (l >> 2);
    int c0 = wc * 32 + (l & 3) * 2;
    #pragma unroll
    for (int mt = 0; mt < 4; mt++) {
        #pragma unroll
        for (int j = 0; j < 4; j++) {
            int row = mbase + r0 + mt * 16;
            int col = nbase + c0 + j * 8;
            float* p0 = C + (size_t)row * N + col;
            float* p1 = C + (size_t)(row + 8) * N + col;
            atomicAdd(p0,     acc[mt][j][0]);
            atomicAdd(p0 + 1, acc[mt][j][1]);
            atomicAdd(p1,     acc[mt][j][2]);
            atomicAdd(p1 + 1, acc[mt][j][3]);
        }
    }
}

// =======================================================================
// Fused MLP: gh = silu(A@Bg^T) * (A@Bu^T), fp16 out. 128x64 tile.
// =======================================================================
__global__ void __launch_bounds__(256, 2) k_mlp(const __half* __restrict__ A,
                                                const __half* __restrict__ Bg,
                                                const __half* __restrict__ Bu,
                                                __half* __restrict__ Cg,
                                                int N, int K) {
    extern __shared__ __align__(128) char smraw[];
    const int mbase = blockIdx.y << 7;
    const int nbase = blockIdx.x << 6;

    const int t = threadIdx.x;
    const int l = t & 31;
    const int w = t >> 5;
    const int wr = w >> 2;
    const int wc = w & 3;
    const unsigned sb = (unsigned)__cvta_generic_to_shared(smraw);

    auto load_stage = [&](int c, int s) {
        unsigned stg = sb + (unsigned)s * 32768u;
        int k0 = c << 6;
        #pragma unroll
        for (int i = 0; i < 4; i++) {
            int id = t + i * 256;
            int row = id >> 3, kc = id & 7;
            unsigned soff = stg + (unsigned)row * 128u + (unsigned)((kc ^ (row & 7)) << 4);
            cpasync16(soff, A + (size_t)(mbase + row) * K + k0 + kc * 8);
        }
        #pragma unroll
        for (int i = 0; i < 2; i++) {
            int id = t + i * 256;
            int row = id >> 3, kc = id & 7;
            unsigned soff = stg + 16384u + (unsigned)row * 128u +
                            (unsigned)((kc ^ (row & 7)) << 4);
            size_t bo = (size_t)(nbase + row) * K + k0 + kc * 8;
            cpasync16(soff,         Bg + bo);
            cpasync16(soff + 8192u, Bu + bo);
        }
        cp_commit();
    };

    float ag[4][2][4], au[4][2][4];
    #pragma unroll
    for (int i = 0; i < 4; i++)
        #pragma unroll
        for (int j = 0; j < 2; j++)
            #pragma unroll
            for (int q = 0; q < 4; q++) { ag[i][j][q] = 0.0f; au[i][j][q] = 0.0f; }

    const int nc = K >> 6;
    load_stage(0, 0);
    load_stage(1, 1);

    for (int c = 0; c < nc; c++) {
        if (c + 1 < nc) cp_wait<1>(); else cp_wait<0>();
        __syncthreads();
        unsigned stg = sb + (unsigned)(c & 1) * 32768u;
        #pragma unroll
        for (int ks = 0; ks < 4; ks++) {
            unsigned aH[4][4], bG[4], bU[4];
            #pragma unroll
            for (int mt = 0; mt < 4; mt++) {
                int row = wr * 64 + mt * 16 + (l & 15);
                int chunk = ks * 2 + (l >> 4);
                unsigned off = stg + (unsigned)row * 128u + (unsigned)((chunk ^ (row & 7)) << 4);
                ldsm4(aH[mt], off);
            }
            {
                int nrow = wc * 16 + ((l >> 1) & 8) + (l & 7);
                int chunk = ks * 2 + ((l >> 3) & 1);
                unsigned off = stg + 16384u + (unsigned)nrow * 128u +
                               (unsigned)((chunk ^ (nrow & 7)) << 4);
                ldsm4(bG, off);
                ldsm4(bU, off + 8192u);
            }
            #pragma unroll
            for (int mt = 0; mt < 4; mt++)
                #pragma unroll
                for (int j = 0; j < 2; j++) {
                    mma16816(ag[mt][j], aH[mt], &bG[j * 2]);
                    mma16816(au[mt][j], aH[mt], &bU[j * 2]);
                }
        }
        __syncthreads();
        if (c + 2 < nc) load_stage(c + 2, c & 1);
    }

    int r0 = wr * 64 + (l >> 2);
    int c0 = wc * 16 + (l & 3) * 2;
    #pragma unroll
    for (int mt = 0; mt < 4; mt++) {
        #pragma unroll
        for (int j = 0; j < 2; j++) {
            int row = mbase + r0 + mt * 16;
            int col = nbase + c0 + j * 8;
            float g0 = ag[mt][j][0], g1 = ag[mt][j][1];
            float g2 = ag[mt][j][2], g3 = ag[mt][j][3];
            float v0 = g0 / (1.0f + expf(-g0)) * au[mt][j][0];
            float v1 = g1 / (1.0f + expf(-g1)) * au[mt][j][1];
            float v2 = g2 / (1.0f + expf(-g2)) * au[mt][j][2];
            float v3 = g3 / (1.0f + expf(-g3)) * au[mt][j][3];
            *(unsigned*)(Cg + (size_t)row * N + col)       = h2u(__floats2half2_rn(v0, v1));
            *(unsigned*)(Cg + (size_t)(row + 8) * N + col) = h2u(__floats2half2_rn(v2, v3));
        }
    }
}

// ---------------- rope + head-major reshape, vectorized (4 halves/thread) ----------------
struct RsOne {
    const __half* src;
    __half*       dst;
    int rows;
    int dstStride;
    int dstOff;
    int posBase;
    float scl;
};
struct RsArgs { RsOne e[11]; };

__global__ void __launch_bounds__(256) k_reshape(RsArgs ra, const float* __restrict__ cosT,
                                                 const float* __restrict__ sinT) {
    RsOne a = ra.e[blockIdx.y];
    int row = blockIdx.x;
    if (row >= a.rows) return;
    int t = threadIdx.x;
    int n = t * 4;              // 4 consecutive elements, same head, same rope half
    int h = n >> 6;
    int d = n & 63;

    const __half* sp = a.src + (size_t)row * 1024 + n;
    uint2 vraw = *(const uint2*)sp;
    __half2 v01 = *(__half2*)&vraw.x;
    __half2 v23 = *(__half2*)&vraw.y;
    float f0 = __low2float(v01), f1 = __high2float(v01);
    float f2 = __low2float(v23), f3 = __high2float(v23);

    float o0, o1, o2, o3;
    if (a.posBase >= 0) {
        int pos = a.posBase + row;
        int pd = (d < 32) ? d + 32 : d - 32;
        float psign = (d < 32) ? -1.0f : 1.0f;
        uint2 praw = *(const uint2*)(a.src + (size_t)row * 1024 + h * 64 + pd);
        __half2 p01 = *(__half2*)&praw.x;
        __half2 p23 = *(__half2*)&praw.y;
        float4 cs = *(const float4*)(cosT + pos * 64 + d);
        float4 sn = *(const float4*)(sinT + pos * 64 + d);
        o0 = f0 * cs.x + psign * __low2float(p01)  * sn.x;
        o1 = f1 * cs.y + psign * __high2float(p01) * sn.y;
        o2 = f2 * cs.z + psign * __low2float(p23)  * sn.z;
        o3 = f3 * cs.w + psign * __high2float(p23) * sn.w;
    } else {
        o0 = f0; o1 = f1; o2 = f2; o3 = f3;
    }
    float s = a.scl;
    __half* dp = a.dst + ((size_t)h * a.dstStride + a.dstOff + row) * 64 + d;
    *(uint2*)dp = make_uint2(h2u(__floats2half2_rn(o0 * s, o1 * s)),
                             h2u(__floats2half2_rn(o2 * s, o3 * s)));
}

// ---------------- HMMA flash attention, z-batched, double-buffered K/V ----------------
struct AtArgs {
    const __half* Q[3];  int nq[3];
    const __half* K1[3]; const __half* V1[3]; int len1[3]; int hs1[3];
    const __half* K2[3]; const __half* V2[3]; int len2[3]; int hs2[3];
    int P[3]; __half* OutH[3];
};

__global__ void __launch_bounds__(128) k_attn(AtArgs aa) {
    const int z = blockIdx.z;
    const int qb = blockIdx.x * 64;
    if (qb >= aa.nq[z]) return;
    const int nq = aa.nq[z], len1 = aa.len1[z], hs1 = aa.hs1[z];
    const int len2 = aa.len2[z], hs2 = aa.hs2[z], P = aa.P[z];
    const __half* K1 = aa.K1[z]; const __half* V1 = aa.V1[z];
    const __half* K2 = aa.K2[z]; const __half* V2 = aa.V2[z];
    __half* OutH = aa.OutH[z];

    const int h = blockIdx.y;
    const int t = threadIdx.x;
    const int l = t & 31;
    const int w = t >> 5;

    __shared__ __align__(16) __half sm[16384];
    const unsigned sb = (unsigned)__cvta_generic_to_shared(sm);

    const __half* Qh = aa.Q[z] + (size_t)h * nq * 64;
    const int qrow = qb + w * 16 + (l >> 2);
    const int qcol = (l & 3) * 2;
    unsigned qfr[4][4];
    #pragma unroll
    for (int dt = 0; dt < 4; dt++) {
        qfr[dt][0] = *(const unsigned*)(Qh + (size_t)qrow * 64 + dt * 16 + qcol);
        qfr[dt][1] = *(const unsigned*)(Qh + (size_t)(qrow + 8) * 64 + dt * 16 + qcol);
        qfr[dt][2] = *(const unsigned*)(Qh + (size_t)qrow * 64 + dt * 16 + 8 + qcol);
        qfr[dt][3] = *(const unsigned*)(Qh + (size_t)(qrow + 8) * 64 + dt * 16 + 8 + qcol);
    }

    float oacc[8][4];
    #pragma unroll
    for (int i = 0; i < 8; i++)
        #pragma unroll
        for (int q = 0; q < 4; q++) oacc[i][q] = 0.0f;
    float m0 = -1e30f, m1 = -1e30f, ls0 = 0.0f, ls1 = 0.0f;

    const int total = len1 + len2;
    const int eff = min(total, P + qb + 64);
    const int ntk = (eff + 63) >> 6;
    const int wqmin = qb + w * 16;

    auto load_kv = [&](int kt, int s) {
        #pragma unroll
        for (int i = 0; i < 4; i++) {
            int id = t + i * 128;
            int row = id >> 3, kc = id & 7;
            int j = kt * 64 + row;
            const __half *kp, *vp;
            if (j < len1) {
                kp = K1 + (size_t)h * hs1 + (size_t)j * 64;
                vp = V1 + (size_t)h * hs1 + (size_t)j * 64;
            } else {
                kp = K2 + (size_t)h * hs2 + (size_t)(j - len1) * 64;
                vp = V2 + (size_t)h * hs2 + (size_t)(j - len1) * 64;
            }
            unsigned soff = sb + (unsigned)s * 16384u + (unsigned)row * 128u +
                            (unsigned)((kc ^ (row & 7)) << 4);
            cpasync16(soff,         kp + kc * 8);
            cpasync16(soff + 8192u, vp + kc * 8);
        }
        cp_commit();
    };

    load_kv(0, 0);

    for (int kt = 0; kt < ntk; kt++) {
        if (kt + 1 < ntk) { load_kv(kt + 1, (kt + 1) & 1); cp_wait<1>(); }
        else cp_wait<0>();
        __syncthreads();
        unsigned stg = sb + (unsigned)(kt & 1) * 16384u;

        float sacc[8][4];
        #pragma unroll
        for (int i = 0; i < 8; i++)
            #pragma unroll
            for (int q = 0; q < 4; q++) sacc[i][q] = 0.0f;
        #pragma unroll
        for (int p = 0; p < 4; p++) {
            int nrow = p * 16 + ((l >> 1) & 8) + (l & 7);
            #pragma unroll
            for (int dt = 0; dt < 4; dt++) {
                int chunk = dt * 2 + ((l >> 3) & 1);
                unsigned off = stg + (unsigned)nrow * 128u + (unsigned)((chunk ^ (nrow & 7)) << 4);
                unsigned kfr[4];
                ldsm4(kfr, off);
                mma16816(sacc[2 * p],     qfr[dt], kfr);
                mma16816(sacc[2 * p + 1], qfr[dt], kfr + 2);
            }
        }

        int kg0 = kt * 64;
        if (!(kg0 + 63 < P || kg0 + 63 - P <= wqmin)) {
            #pragma unroll
            for (int nt = 0; nt < 8; nt++) {
                int col = kg0 + nt * 8 + qcol;
                if (!(col < P || col - P <= qrow))         sacc[nt][0] = -1e30f;
                if (!(col + 1 < P || col + 1 - P <= qrow)) sacc[nt][1] = -1e30f;
                if (!(col < P || col - P <= qrow + 8))         sacc[nt][2] = -1e30f;
                if (!(col + 1 < P || col + 1 - P <= qrow + 8)) sacc[nt][3] = -1e30f;
            }
        }

        float tm0 = -1e30f, tm1 = -1e30f;
        #pragma unroll
        for (int nt = 0; nt < 8; nt++) {
            tm0 = fmaxf(tm0, fmaxf(sacc[nt][0], sacc[nt][1]));
            tm1 = fmaxf(tm1, fmaxf(sacc[nt][2], sacc[nt][3]));
        }
        tm0 = fmaxf(tm0, __shfl_xor_sync(0xffffffffu, tm0, 1));
        tm0 = fmaxf(tm0, __shfl_xor_sync(0xffffffffu, tm0, 2));
        tm1 = fmaxf(tm1, __shfl_xor_sync(0xffffffffu, tm1, 1));
        tm1 = fmaxf(tm1, __shfl_xor_sync(0xffffffffu, tm1, 2));
        float nm0 = fmaxf(m0, tm0), nm1 = fmaxf(m1, tm1);
        float cr0 = __expf(m0 - nm0), cr1 = __expf(m1 - nm1);
        ls0 *= cr0; ls1 *= cr1;
        #pragma unroll
        for (int nt = 0; nt < 8; nt++) {
            oacc[nt][0] *= cr0; oacc[nt][1] *= cr0;
            oacc[nt][2] *= cr1; oacc[nt][3] *= cr1;
        }
        m0 = nm0; m1 = nm1;
        #pragma unroll
        for (int nt = 0; nt < 8; nt++) {
            sacc[nt][0] = __expf(sacc[nt][0] - nm0);
            sacc[nt][1] = __expf(sacc[nt][1] - nm0);
            sacc[nt][2] = __expf(sacc[nt][2] - nm1);
            sacc[nt][3] = __expf(sacc[nt][3] - nm1);
            ls0 += sacc[nt][0] + sacc[nt][1];
            ls1 += sacc[nt][2] + sacc[nt][3];
        }

        #pragma unroll
        for (int kt2 = 0; kt2 < 4; kt2++) {
            unsigned pfr[4];
            pfr[0] = h2u(__floats2half2_rn(sacc[2 * kt2][0],     sacc[2 * kt2][1]));
            pfr[1] = h2u(__floats2half2_rn(sacc[2 * kt2][2],     sacc[2 * kt2][3]));
            pfr[2] = h2u(__floats2half2_rn(sacc[2 * kt2 + 1][0], sacc[2 * kt2 + 1][1]));
            pfr[3] = h2u(__floats2half2_rn(sacc[2 * kt2 + 1][2], sacc[2 * kt2 + 1][3]));
            int vrow = kt2 * 16 + (l & 15);
            #pragma unroll
            for (int dv = 0; dv < 4; dv++) {
                int chunk = dv * 2 + (l >> 4);
                unsigned off = stg + 8192u + (unsigned)vrow * 128u +
                               (unsigned)((chunk ^ (vrow & 7)) << 4);
                unsigned vf4[4];
                ldsm4t(vf4, off);
                mma16816(oacc[2 * dv],     pfr, vf4);
                mma16816(oacc[2 * dv + 1], pfr, vf4 + 2);
            }
        }
        __syncthreads();
    }

    ls0 += __shfl_xor_sync(0xffffffffu, ls0, 1);
    ls0 += __shfl_xor_sync(0xffffffffu, ls0, 2);
    ls1 += __shfl_xor_sync(0xffffffffu, ls1, 1);
    ls1 += __shfl_xor_sync(0xffffffffu, ls1, 2);
    float inv0 = 1.0f / ls0, inv1 = 1.0f / ls1;
    __half* op0 = OutH + (size_t)qrow * 1024 + h * 64 + qcol;
    __half* op1 = OutH + (size_t)(qrow + 8) * 1024 + h * 64 + qcol;
    #pragma unroll
    for (int nt = 0; nt < 8; nt++) {
        *(unsigned*)(op0 + nt * 8) = h2u(__floats2half2_rn(oacc[nt][0] * inv0,
                                                           oacc[nt][1] * inv0));
        *(unsigned*)(op1 + nt * 8) = h2u(__floats2half2_rn(oacc[nt][2] * inv1,
                                                           oacc[nt][3] * inv1));
    }
}

// ---------------- host driver ----------------
extern "C" void kernel_launch(void* const* d_in, const int* in_sizes, int n_in,
                              void* d_out, int out_size) {
    (void)in_sizes; (void)n_in; (void)out_size;

    const int*   ids    = (const int*)  d_in[0];
    const float* memory = (const float*)d_in[1];
    const float* beacon = (const float*)d_in[2];
    const float* forget = (const float*)d_in[3];
    const float* embed  = (const float*)d_in[4];
    const float* ln1    = (const float*)d_in[5];
    const float* ln2    = (const float*)d_in[6];
    const float* Wsrc[12] = {
        (const float*)d_in[7],  (const float*)d_in[8],  (const float*)d_in[9],
        (const float*)d_in[10], (const float*)d_in[11], (const float*)d_in[12],
        (const float*)d_in[13], (const float*)d_in[14], (const float*)d_in[15],
        (const float*)d_in[16], (const float*)d_in[17], (const float*)d_in[18]
    };
    const float* Wg = (const float*)d_in[19];
    const float* Wu = (const float*)d_in[20];
    const float* Wd = (const float*)d_in[21];
    float* out = (float*)d_out;

    float* pool = nullptr;
    cudaGetSymbolAddress((void**)&pool, g_pool);
    __half* hp = nullptr;
    cudaGetSymbolAddress((void**)&hp, g_poolhf);

    float* cat  = pool + OFF_CAT;
    float* cosT = pool + OFF_COS;
    float* sinT = pool + OFF_SIN;
    __half* tqkv_h = (__half*)(pool + OFF_TQKV);
    __half* tsm_h  = tqkv_h + 3u * 1048576u;

    __half* xh = hp + B_XH;
    __half* ah = hp + B_AH;
    __half* yh = hp + B_YH;
    __half* gh = hp + B_GH;
    __half* mehAll = hp + B_MEH;
    __half* qh   = hp + HB_Q;
    __half* qbh  = hp + HB_QB;
    __half* qfh  = hp + HB_QF;
    __half* kbuf = hp + HB_K;
    __half* vbuf = hp + HB_V;
    __half* kf   = hp + HB_KF;
    __half* vf   = hp + HB_VF;

    cudaFuncSetAttribute(k_hmma,    cudaFuncAttributeMaxDynamicSharedMemorySize, SMEM_HM);
    cudaFuncSetAttribute(k_hmma_sk, cudaFuncAttributeMaxDynamicSharedMemorySize, SMEM_HM);
    cudaFuncSetAttribute(k_mlp,     cudaFuncAttributeMaxDynamicSharedMemorySize, SMEM_HM);

    const size_t WDD = (size_t)D * D;
    const size_t WDF = (size_t)D * F;
    const size_t WFD = (size_t)F * D;
    const size_t MDsz = (size_t)Mm * D;

    // ---- pre-loop ----
    k_tables<<<(1280 * 64 + 255) / 256, 256>>>(cosT, sinT);
    k_fillcat<<<(TOT * D + 255) / 256, 256>>>(cat, ids, embed, beacon, forget);
    {
        WcArgs wa;
        int off = 0;
        for (int i = 0; i < 12; i++) {
            wa.e[i] = { Wsrc[i], hp + BW_ALL + (size_t)i * 1048576, D, D, off, WDD };
            off += (D / 64) * (D / 64);          // 256 each
        }
        wa.e[12] = { Wg, hp + BW_ALL + 12582912, D, F, off, WDF }; off += (D/64)*(F/64);
        wa.e[13] = { Wu, hp + BW_ALL + 14680064, D, F, off, WDF }; off += (D/64)*(F/64);
        wa.e[14] = { Wd, hp + BW_ALL + 16777216, F, D, off, WFD }; off += (F/64)*(D/64);
        k_wconv<<<dim3(off, L), 256>>>(wa);      // (4608, 8)
    }
    k_split<<<(L * Mm * D / 8 + 255) / 256, 256>>>(memory, mehAll, L * Mm * D);

    for (int l = 0; l < L; l++) {
        const float* mem_l = memory + (size_t)l * MDsz;
        __half* base_w = hp + BW_ALL + (size_t)l * WL_STRIDE;
        __half* wtH[15];
        for (int i = 0; i < 12; i++) wtH[i] = base_w + (size_t)i * 1048576;
        wtH[12] = base_w + 12582912;
        wtH[13] = base_w + 14680064;
        wtH[14] = base_w + 16777216;
        __half* meh = mehAll + (size_t)l * MDsz;

        k_rms<<<TOT + Mm, 256>>>(cat, ln1 + (size_t)l * D, xh,
                                 mem_l, out + (size_t)l * MDsz);

        // QKV + eight 128-row projections -> fp16 outputs
        {
            GArgs ga = {};
            for (int z = 0; z < 3; z++) {
                ga.Ah[z] = xh;
                ga.Bh[z] = wtH[z];
                ga.Ch[z] = tqkv_h + (size_t)z * 1048576;
                ga.mRows[z] = S;
            }
            const __half* bxh = xh + (size_t)S * D;
            const __half* fxh = xh + (size_t)(S + Mm) * D;
            const __half* sAh[8] = { meh, meh, bxh, bxh, bxh, fxh, fxh, fxh };
            int wmap[8] = {4, 5, 6, 7, 8, 9, 10, 11};
            for (int z = 0; z < 8; z++) {
                ga.Ah[3 + z] = sAh[z];
                ga.Bh[3 + z] = wtH[wmap[z]];
                ga.Ch[3 + z] = tsm_h + (size_t)z * 131072;
                ga.mRows[3 + z] = Mm;
            }
            k_hmma<<<dim3(8, 8, 11), 256, SMEM_HM>>>(ga, D, D, 0, 1);
        }
        // rope + reshape (vectorized; Q scaled by 0.125)
        {
            RsArgs ra;
            ra.e[0]  = { tqkv_h,            qh,   S,  1024, 0,    Mm,   0.125f };
            ra.e[1]  = { tqkv_h + 1048576,  kbuf, S,  1280, 128,  Mm,   1.0f };
            ra.e[2]  = { tqkv_h + 2097152,  vbuf, S,  1280, 128,  -1,   1.0f };
            ra.e[3]  = { tsm_h,             kbuf, Mm, 1280, 0,    0,    1.0f };
            ra.e[4]  = { tsm_h + 131072,    vbuf, Mm, 1280, 0,    -1,   1.0f };
            ra.e[5]  = { tsm_h + 262144,    qbh,  Mm, 128,  0,    KHID, 0.125f };
            ra.e[6]  = { tsm_h + 393216,    kbuf, Mm, 1280, KHID, KHID, 1.0f };
            ra.e[7]  = { tsm_h + 524288,    vbuf, Mm, 1280, KHID, -1,   1.0f };
            ra.e[8]  = { tsm_h + 655360,    qfh,  Mm, 128,  0,    KHID, 0.125f };
            ra.e[9]  = { tsm_h + 786432,    kf,   Mm, 128,  0,    KHID, 1.0f };
            ra.e[10] = { tsm_h + 917504,    vf,   Mm, 128,  0,    -1,   1.0f };
            k_reshape<<<dim3(1024, 11), 256>>>(ra, cosT, sinT);
        }
        // attention
        {
            AtArgs aa;
            aa.Q[0] = qh;    aa.nq[0] = S;
            aa.K1[0] = kbuf; aa.V1[0] = vbuf; aa.len1[0] = KHID; aa.hs1[0] = 1280 * 64;
            aa.K2[0] = kf;   aa.V2[0] = vf;   aa.len2[0] = 0;    aa.hs2[0] = 128 * 64;
            aa.P[0] = Mm;    aa.OutH[0] = ah;
            aa.Q[1] = qbh;   aa.nq[1] = Mm;
            aa.K1[1] = kbuf; aa.V1[1] = vbuf; aa.len1[1] = TOT;  aa.hs1[1] = 1280 * 64;
            aa.K2[1] = kf;   aa.V2[1] = vf;   aa.len2[1] = 0;    aa.hs2[1] = 128 * 64;
            aa.P[1] = KHID;  aa.OutH[1] = ah + (size_t)S * D;
            aa.Q[2] = qfh;   aa.nq[2] = Mm;
            aa.K1[2] = kbuf; aa.V1[2] = vbuf; aa.len1[2] = KHID; aa.hs1[2] = 1280 * 64;
            aa.K2[2] = kf;   aa.V2[2] = vf;   aa.len2[2] = Mm;   aa.hs2[2] = 128 * 64;
            aa.P[2] = KHID;  aa.OutH[2] = ah + (size_t)KHID * D;
            k_attn<<<dim3(S / 64, H, 3), 128>>>(aa);
        }
        // Wo (+residual already in cat) — split-K=4
        k_hmma_sk<<<dim3(8, 10, 4), 256, SMEM_HM>>>(ah, wtH[3], cat, D, D, 4);
        k_rms<<<TOT, 256>>>(cat, ln2 + (size_t)l * D, yh, nullptr, nullptr);
        // fused MLP
        k_mlp<<<dim3(F / 64, TOT / 128), 256, SMEM_HM>>>(yh, wtH[12], wtH[13], gh, F, D);
        // down (+residual already in cat) — split-K=4
        k_hmma_sk<<<dim3(8, 10, 4), 256, SMEM_HM>>>(gh, wtH[14], cat, D, F, 4);
    }
}